// round 15
// baseline (speedup 1.0000x reference)
#include <cuda_runtime.h>
#include <cuda_fp16.h>
#include <math.h>
#include <stdint.h>

#define BB   8
#define DD   1024
#define NPTS 4096
#define KK   64
#define HH   512

#define SEPS 1e-3f
#define INV_EPS (1.0f/1e-3f)

// ---------------- scratch (device globals; no allocation) ----------------
static __device__ float g_y1[BB*HH*NPTS];
static __device__ float g_y2[BB*HH*NPTS];
static __device__ float g_ls[BB*KK*NPTS];
static __device__ float g_score[BB*KK*NPTS];
static __device__ float g_lsn[BB*NPTS];
static __device__ float g_pi[BB*KK];
static __device__ float g_sc1[HH], g_sh1[HH], g_sc2[HH], g_sh2[HH];
static __device__ float g_muxyz[BB*3*KK];
static __device__ float g_muT[BB*KK*DD];
static __device__ float g_invf[BB*NPTS];
static __device__ float g_invmu[BB*KK];
static __device__ float g_costx[BB*NPTS*KK];
static __device__ float g_costxT[BB*KK*NPTS];
static __device__ float g_costf[BB*NPTS*KK];
static __device__ float g_costfT[BB*KK*NPTS];
static __device__ float g_u[2*BB*NPTS];
static __device__ float g_v[2*BB*KK];
static __device__ float g_acc[4];
// half hi/lo operand arrays
static __device__ __half g_fh[BB*DD*NPTS],  g_fl[BB*DD*NPTS];
static __device__ __half g_y1h[BB*HH*NPTS], g_y1l[BB*HH*NPTS];
static __device__ __half g_y2h[BB*HH*NPTS], g_y2l[BB*HH*NPTS];
static __device__ __half g_sch[BB*KK*NPTS], g_scl[BB*KK*NPTS];
static __device__ __half g_w1h[HH*DD], g_w1l[HH*DD];
static __device__ __half g_w2h[HH*HH], g_w2l[HH*HH];
static __device__ __half g_w3h[KK*HH], g_w3l[KK*HH];
static __device__ __half g_muTh[BB*KK*DD], g_muTl[BB*KK*DD];

// ================= fp16x3 helpers =================
__device__ __forceinline__ uint32_t split2h(float a, float b) {
    __half2 t = __halves2half2(__float2half_rn(a), __float2half_rn(b));
    return *reinterpret_cast<uint32_t*>(&t);
}
__device__ __forceinline__ uint32_t split2l(float a, float b) {
    __half ha = __float2half_rn(a), hb = __float2half_rn(b);
    float ra = a - __half2float(ha), rb = b - __half2float(hb);
    __half2 t = __halves2half2(__float2half_rn(ra), __float2half_rn(rb));
    return *reinterpret_cast<uint32_t*>(&t);
}

#define MMAH(d, a, b) \
    asm volatile("mma.sync.aligned.m16n8k16.row.col.f32.f16.f16.f32 " \
        "{%0,%1,%2,%3}, {%4,%5,%6,%7}, {%8,%9}, {%0,%1,%2,%3};" \
        : "+f"((d)[0]), "+f"((d)[1]), "+f"((d)[2]), "+f"((d)[3]) \
        : "r"((a).x), "r"((a).y), "r"((a).z), "r"((a).w), "r"((b).x), "r"((b).y))

// ================= converters =================
__global__ void convert_pair_kernel(const float* __restrict__ src,
                                    __half* __restrict__ dh, __half* __restrict__ dl,
                                    size_t n4)
{
    size_t i4 = (size_t)blockIdx.x * blockDim.x + threadIdx.x;
    if (i4 >= n4) return;
    float4 v = ((const float4*)src)[i4];
    uint2 h, l;
    h.x = split2h(v.x, v.y); h.y = split2h(v.z, v.w);
    l.x = split2l(v.x, v.y); l.y = split2l(v.z, v.w);
    ((uint2*)dh)[i4] = h;
    ((uint2*)dl)[i4] = l;
}

// ================= main 3xFP16 GEMM (TN), pre-split half inputs =================
// C[b][m][n] = sum_k W[m][k] X[b][k][n]; mode 0: +bias; mode 1: cost-fea epilogue.
#define BUFW 4224   // Ah[0,1024) Al[1024,2048) Bh[2048,3136) Bl[3136,4224)

__global__ __launch_bounds__(256, 2)
void mma_gemm_kernel(const __half* __restrict__ Wh, const __half* __restrict__ Wl,
                     const __half* __restrict__ Xh, const __half* __restrict__ Xl,
                     const float* __restrict__ bias, float* __restrict__ C,
                     int Kd, int Mtot, int wstride, int mode,
                     const float* __restrict__ invf, const float* __restrict__ invmu)
{
    __shared__ uint32_t sm[2 * BUFW];
    const int tid = threadIdx.x, wid = tid >> 5, lane = tid & 31;
    const int wm = wid >> 2, wn = wid & 3;
    const int g = lane >> 2, tg = lane & 3;
    const int b = blockIdx.z, n0 = blockIdx.x * 128, m0 = blockIdx.y * 128;
    const __half* Whb = Wh + (size_t)b * wstride;
    const __half* Wlb = Wl + (size_t)b * wstride;
    const __half* Xhb = Xh + (size_t)b * Kd * NPTS;
    const __half* Xlb = Xl + (size_t)b * Kd * NPTS;
    float* Cb = C + (size_t)b * Mtot * NPTS;

    float acc[4][4][4];
#pragma unroll
    for (int i = 0; i < 4; i++)
#pragma unroll
        for (int j = 0; j < 4; j++)
#pragma unroll
            for (int r = 0; r < 4; r++) acc[i][j][r] = 0.0f;

    const int CH = Kd / 16;

    // A slot task: mtg=tid>>5, slot s=tid&31 (g'=s>>2 row, tg'=s&3 kpair)
    const int s_mtg = tid >> 5, s_s = tid & 31;
    const int s_g = s_s >> 2, s_tg = s_s & 3;
    // B task: kp=tid>>5, n4=tid&31
    const int b_kp = tid >> 5, b_n4 = tid & 31;

    uint32_t awh[4], awl[4];
    uint2 b0h, b1h, b0l, b1l;

    auto ldg_regs = [&](int k0) {
        int r0 = m0 + s_mtg * 16 + s_g;     if (r0 >= Mtot) r0 -= Mtot;
        int r1 = m0 + s_mtg * 16 + s_g + 8; if (r1 >= Mtot) r1 -= Mtot;
        const __half* p0h = Whb + (size_t)r0 * Kd + k0 + 2 * s_tg;
        const __half* p1h = Whb + (size_t)r1 * Kd + k0 + 2 * s_tg;
        const __half* p0l = Wlb + (size_t)r0 * Kd + k0 + 2 * s_tg;
        const __half* p1l = Wlb + (size_t)r1 * Kd + k0 + 2 * s_tg;
        awh[0] = *(const uint32_t*)(p0h);
        awh[1] = *(const uint32_t*)(p1h);
        awh[2] = *(const uint32_t*)(p0h + 8);
        awh[3] = *(const uint32_t*)(p1h + 8);
        awl[0] = *(const uint32_t*)(p0l);
        awl[1] = *(const uint32_t*)(p1l);
        awl[2] = *(const uint32_t*)(p0l + 8);
        awl[3] = *(const uint32_t*)(p1l + 8);
        const __half* pbh = Xhb + (size_t)(k0 + 2 * b_kp) * NPTS + n0 + b_n4 * 4;
        const __half* pbl = Xlb + (size_t)(k0 + 2 * b_kp) * NPTS + n0 + b_n4 * 4;
        b0h = *(const uint2*)(pbh);
        b1h = *(const uint2*)(pbh + NPTS);
        b0l = *(const uint2*)(pbl);
        b1l = *(const uint2*)(pbl + NPTS);
    };

    auto sts_smem = [&](int buf) {
        uint32_t* Ah = sm + buf * BUFW;
        uint32_t* Al = Ah + 1024;
        uint32_t* Bh = Ah + 2048;
        uint32_t* Bl = Ah + 3136;
        *(uint4*)(Ah + s_mtg * 128 + s_s * 4) = make_uint4(awh[0], awh[1], awh[2], awh[3]);
        *(uint4*)(Al + s_mtg * 128 + s_s * 4) = make_uint4(awl[0], awl[1], awl[2], awl[3]);
        uint4 w;
        w.x = __byte_perm(b0h.x, b1h.x, 0x5410);
        w.y = __byte_perm(b0h.x, b1h.x, 0x7632);
        w.z = __byte_perm(b0h.y, b1h.y, 0x5410);
        w.w = __byte_perm(b0h.y, b1h.y, 0x7632);
        *(uint4*)(Bh + b_kp * 136 + b_n4 * 4) = w;
        w.x = __byte_perm(b0l.x, b1l.x, 0x5410);
        w.y = __byte_perm(b0l.x, b1l.x, 0x7632);
        w.z = __byte_perm(b0l.y, b1l.y, 0x5410);
        w.w = __byte_perm(b0l.y, b1l.y, 0x7632);
        *(uint4*)(Bl + b_kp * 136 + b_n4 * 4) = w;
    };

    ldg_regs(0);
    sts_smem(0);
    __syncthreads();

    for (int c = 0; c < CH; c++) {
        int p = c & 1;
        if (c + 1 < CH) ldg_regs((c + 1) * 16);

        const uint32_t* Ah = sm + p * BUFW;
        const uint32_t* Al = Ah + 1024;
        const uint32_t* Bh = Ah + 2048;
        const uint32_t* Bl = Ah + 3136;

        uint2 bh[4], bl[4];
#pragma unroll
        for (int nt = 0; nt < 4; nt++) {
            int n = g + (wn * 4 + nt) * 8;
            bh[nt].x = Bh[tg * 136 + n];
            bh[nt].y = Bh[(tg + 4) * 136 + n];
            bl[nt].x = Bl[tg * 136 + n];
            bl[nt].y = Bl[(tg + 4) * 136 + n];
        }
#pragma unroll
        for (int mt = 0; mt < 4; mt++) {
            int o = (wm * 4 + mt) * 128 + lane * 4;
            uint4 ah = *(const uint4*)(Ah + o);
            uint4 al = *(const uint4*)(Al + o);
#pragma unroll
            for (int nt = 0; nt < 4; nt++) {
                MMAH(acc[mt][nt], ah, bh[nt]);
                MMAH(acc[mt][nt], ah, bl[nt]);
                MMAH(acc[mt][nt], al, bh[nt]);
            }
        }

        if (c + 1 < CH) sts_smem(1 - p);
        __syncthreads();
    }

    // epilogue
#pragma unroll
    for (int mt = 0; mt < 4; mt++) {
        int mrow = m0 + wm * 64 + mt * 16 + g;
#pragma unroll
        for (int half = 0; half < 2; half++) {
            int mg = mrow + half * 8;
            if (mg < Mtot) {
                float* crow = Cb + (size_t)mg * NPTS + n0 + wn * 32 + tg * 2;
                if (mode == 0) {
                    float bi = bias[mg];
#pragma unroll
                    for (int nt = 0; nt < 4; nt++) {
                        float2 vv;
                        vv.x = acc[mt][nt][half * 2 + 0] + bi;
                        vv.y = acc[mt][nt][half * 2 + 1] + bi;
                        *(float2*)(crow + nt * 8) = vv;
                    }
                } else {
                    float im = invmu[b * KK + mg] * 2.0f;
                    const float* fr = invf + b * NPTS + n0 + wn * 32 + tg * 2;
#pragma unroll
                    for (int nt = 0; nt < 4; nt++) {
                        float2 f2 = *(const float2*)(fr + nt * 8);
                        float2 vv;
                        vv.x = 2.0f - acc[mt][nt][half * 2 + 0] * f2.x * im;
                        vv.y = 2.0f - acc[mt][nt][half * 2 + 1] * f2.y * im;
                        *(float2*)(crow + nt * 8) = vv;
                    }
                }
            }
        }
    }
}

// ================= NT fp16x3 GEMM: MuT[b][k][d] from pre-split halves ==========
#define NTBUFW 3200  // Ah[0,512) Al[512,1024) Bh[1024,2112) Bl[2112,3200)

__global__ __launch_bounds__(256, 2)
void mma_nt_kernel(const __half* __restrict__ Sh, const __half* __restrict__ Sl,
                   const __half* __restrict__ Fh, const __half* __restrict__ Fl,
                   const float* __restrict__ pi, float* __restrict__ MuT,
                   __half* __restrict__ MuTh, __half* __restrict__ MuTl)
{
    __shared__ uint32_t sm[2 * NTBUFW];
    const int tid = threadIdx.x, wid = tid >> 5, lane = tid & 31;
    const int g = lane >> 2, tg = lane & 3;
    const int b = blockIdx.z, n0 = blockIdx.x * 128;
    const __half* Sbh = Sh + (size_t)b * KK * NPTS;
    const __half* Sbl = Sl + (size_t)b * KK * NPTS;
    const __half* Fbh = Fh + (size_t)b * DD * NPTS;
    const __half* Fbl = Fl + (size_t)b * DD * NPTS;

    float acc[4][2][4];
#pragma unroll
    for (int i = 0; i < 4; i++)
#pragma unroll
        for (int j = 0; j < 2; j++)
#pragma unroll
            for (int r = 0; r < 4; r++) acc[i][j][r] = 0.0f;

    // A slots (threads 0..127): mt=tid>>5, s=tid&31; B rows (threads 128..255): d=tid-128
    const int a_mt = tid >> 5, a_s = tid & 31;
    const int a_g = a_s >> 2, a_tg = a_s & 3;
    const int b_d = tid - 128;

    uint32_t awh[4], awl[4];
    uint4 q0h, q1h, q0l, q1l;

    auto ldg_regs = [&](int k0) {
        if (tid < 128) {
            int r0 = a_mt * 16 + a_g;
            int r1 = r0 + 8;
            const __half* p0h = Sbh + (size_t)r0 * NPTS + k0 + 2 * a_tg;
            const __half* p1h = Sbh + (size_t)r1 * NPTS + k0 + 2 * a_tg;
            const __half* p0l = Sbl + (size_t)r0 * NPTS + k0 + 2 * a_tg;
            const __half* p1l = Sbl + (size_t)r1 * NPTS + k0 + 2 * a_tg;
            awh[0] = *(const uint32_t*)(p0h);
            awh[1] = *(const uint32_t*)(p1h);
            awh[2] = *(const uint32_t*)(p0h + 8);
            awh[3] = *(const uint32_t*)(p1h + 8);
            awl[0] = *(const uint32_t*)(p0l);
            awl[1] = *(const uint32_t*)(p1l);
            awl[2] = *(const uint32_t*)(p0l + 8);
            awl[3] = *(const uint32_t*)(p1l + 8);
        } else {
            const __half* ph = Fbh + (size_t)(n0 + b_d) * NPTS + k0;
            const __half* pl = Fbl + (size_t)(n0 + b_d) * NPTS + k0;
            q0h = *(const uint4*)(ph);
            q1h = *(const uint4*)(ph + 8);
            q0l = *(const uint4*)(pl);
            q1l = *(const uint4*)(pl + 8);
        }
    };

    auto sts_smem = [&](int buf) {
        uint32_t* Ah = sm + buf * NTBUFW;
        uint32_t* Al = Ah + 512;
        uint32_t* Bh = Ah + 1024;
        uint32_t* Bl = Ah + 2112;
        if (tid < 128) {
            *(uint4*)(Ah + a_mt * 128 + a_s * 4) = make_uint4(awh[0], awh[1], awh[2], awh[3]);
            *(uint4*)(Al + a_mt * 128 + a_s * 4) = make_uint4(awl[0], awl[1], awl[2], awl[3]);
        } else {
            Bh[0 * 136 + b_d] = q0h.x;  Bh[1 * 136 + b_d] = q0h.y;
            Bh[2 * 136 + b_d] = q0h.z;  Bh[3 * 136 + b_d] = q0h.w;
            Bh[4 * 136 + b_d] = q1h.x;  Bh[5 * 136 + b_d] = q1h.y;
            Bh[6 * 136 + b_d] = q1h.z;  Bh[7 * 136 + b_d] = q1h.w;
            Bl[0 * 136 + b_d] = q0l.x;  Bl[1 * 136 + b_d] = q0l.y;
            Bl[2 * 136 + b_d] = q0l.z;  Bl[3 * 136 + b_d] = q0l.w;
            Bl[4 * 136 + b_d] = q1l.x;  Bl[5 * 136 + b_d] = q1l.y;
            Bl[6 * 136 + b_d] = q1l.z;  Bl[7 * 136 + b_d] = q1l.w;
        }
    };

    ldg_regs(0);
    sts_smem(0);
    __syncthreads();

    const int CH = NPTS / 16;
    for (int c = 0; c < CH; c++) {
        int p = c & 1;
        if (c + 1 < CH) ldg_regs((c + 1) * 16);

        const uint32_t* Ah = sm + p * NTBUFW;
        const uint32_t* Al = Ah + 512;
        const uint32_t* Bh = Ah + 1024;
        const uint32_t* Bl = Ah + 2112;

        uint2 bh[2], bl[2];
#pragma unroll
        for (int nt = 0; nt < 2; nt++) {
            int n = wid * 16 + nt * 8 + g;
            bh[nt].x = Bh[tg * 136 + n];
            bh[nt].y = Bh[(tg + 4) * 136 + n];
            bl[nt].x = Bl[tg * 136 + n];
            bl[nt].y = Bl[(tg + 4) * 136 + n];
        }
#pragma unroll
        for (int mt = 0; mt < 4; mt++) {
            int o = mt * 128 + lane * 4;
            uint4 ah = *(const uint4*)(Ah + o);
            uint4 al = *(const uint4*)(Al + o);
#pragma unroll
            for (int nt = 0; nt < 2; nt++) {
                MMAH(acc[mt][nt], ah, bh[nt]);
                MMAH(acc[mt][nt], ah, bl[nt]);
                MMAH(acc[mt][nt], al, bh[nt]);
            }
        }

        if (c + 1 < CH) sts_smem(1 - p);
        __syncthreads();
    }

#pragma unroll
    for (int mt = 0; mt < 4; mt++) {
#pragma unroll
        for (int half = 0; half < 2; half++) {
            int m = mt * 16 + g + half * 8;
            float ip = 1.0f / pi[b * KK + m];
            size_t base = ((size_t)b * KK + m) * DD + n0 + wid * 16 + tg * 2;
#pragma unroll
            for (int nt = 0; nt < 2; nt++) {
                float2 vv;
                vv.x = acc[mt][nt][half * 2 + 0] * ip;
                vv.y = acc[mt][nt][half * 2 + 1] * ip;
                *(float2*)(MuT + base + nt * 8) = vv;
                *(uint32_t*)(MuTh + base + nt * 8) = split2h(vv.x, vv.y);
                *(uint32_t*)(MuTl + base + nt * 8) = split2l(vv.x, vv.y);
            }
        }
    }
}

// ================= remaining kernels =================
__global__ void init_kernel() {
    int i = blockIdx.x * blockDim.x + threadIdx.x;
    if (i < 2*BB*NPTS) g_u[i] = 0.0f;
    if (i < 2*BB*KK)   g_v[i] = 0.0f;
    if (i < 4)         g_acc[i] = 0.0f;
}

__global__ void bn_stats_kernel(const float* __restrict__ y,
                                const float* __restrict__ g, const float* __restrict__ be,
                                float* __restrict__ sc, float* __restrict__ sh)
{
    int h = blockIdx.x;
    int tid = threadIdx.x;
    float s = 0.0f, s2 = 0.0f;
    for (int b = 0; b < BB; b++) {
        const float* p = y + ((size_t)(b*HH + h)) * NPTS;
        for (int n = tid; n < NPTS; n += 256) { float v = p[n]; s += v; s2 += v*v; }
    }
    __shared__ float r1[256], r2[256];
    r1[tid] = s; r2[tid] = s2; __syncthreads();
    for (int o = 128; o > 0; o >>= 1) {
        if (tid < o) { r1[tid] += r1[tid+o]; r2[tid] += r2[tid+o]; }
        __syncthreads();
    }
    if (tid == 0) {
        float inv = 1.0f / (float)(BB*NPTS);
        float mean = r1[0] * inv;
        float var  = r2[0] * inv - mean*mean;
        float scale = g[h] / sqrtf(var + 1e-5f);
        sc[h] = scale;
        sh[h] = be[h] - mean * scale;
    }
}

// BN+ReLU, emitting half hi/lo pair (no float writeback)
__global__ void bn_relu_kernel(const float* __restrict__ y,
                               __half* __restrict__ yh, __half* __restrict__ yl,
                               const float* __restrict__ sc, const float* __restrict__ sh)
{
    size_t i4 = (size_t)blockIdx.x * blockDim.x + threadIdx.x;
    size_t total4 = (size_t)BB*HH*NPTS/4;
    if (i4 >= total4) return;
    int h = (int)((i4 / (NPTS/4)) % HH);
    float s = sc[h], t = sh[h];
    float4 v = ((const float4*)y)[i4];
    v.x = fmaxf(0.0f, v.x*s + t);
    v.y = fmaxf(0.0f, v.y*s + t);
    v.z = fmaxf(0.0f, v.z*s + t);
    v.w = fmaxf(0.0f, v.w*s + t);
    uint2 hh, ll;
    hh.x = split2h(v.x, v.y); hh.y = split2h(v.z, v.w);
    ll.x = split2l(v.x, v.y); ll.y = split2l(v.z, v.w);
    ((uint2*)yh)[i4] = hh;
    ((uint2*)yl)[i4] = ll;
}

__global__ void softmax_kernel() {
    int b = blockIdx.y;
    int n = blockIdx.x * 256 + threadIdx.x;
    const float* base = g_ls + (size_t)b*KK*NPTS + n;
    float mx = -1e30f;
#pragma unroll
    for (int k = 0; k < KK; k++) mx = fmaxf(mx, base[(size_t)k*NPTS]);
    float s = 0.0f;
#pragma unroll
    for (int k = 0; k < KK; k++) s += __expf(base[(size_t)k*NPTS] - mx);
    float inv = 1.0f / s;
    float* sb = g_score + (size_t)b*KK*NPTS + n;
    __half* sbh = g_sch + (size_t)b*KK*NPTS + n;
    __half* sbl = g_scl + (size_t)b*KK*NPTS + n;
#pragma unroll
    for (int k = 0; k < KK; k++) {
        float sc = __expf(base[(size_t)k*NPTS] - mx) * inv;
        sb[(size_t)k*NPTS] = sc;
        __half hv = __float2half_rn(sc);
        sbh[(size_t)k*NPTS] = hv;
        sbl[(size_t)k*NPTS] = __float2half_rn(sc - __half2float(hv));
    }
    g_lsn[b*NPTS + n] = mx + logf(s);
}

__global__ void pi_kernel() {
    int k = blockIdx.x, b = blockIdx.y, tid = threadIdx.x;
    const float* p = g_score + (size_t)(b*KK + k) * NPTS;
    float s = 0.0f;
    for (int n = tid; n < NPTS; n += 256) s += p[n];
    __shared__ float r[256];
    r[tid] = s; __syncthreads();
    for (int o = 128; o > 0; o >>= 1) { if (tid < o) r[tid] += r[tid+o]; __syncthreads(); }
    if (tid == 0) g_pi[b*KK + k] = fmaxf(r[0], 1e-4f);
}

__global__ void mu_xyz_kernel(const float* __restrict__ xyz) {
    int k = blockIdx.x, b = blockIdx.y, tid = threadIdx.x;
    const float* sp = g_score + (size_t)(b*KK + k) * NPTS;
    const float* x0 = xyz + (size_t)(b*3 + 0) * NPTS;
    const float* x1 = xyz + (size_t)(b*3 + 1) * NPTS;
    const float* x2 = xyz + (size_t)(b*3 + 2) * NPTS;
    float a0 = 0, a1 = 0, a2 = 0;
    for (int n = tid; n < NPTS; n += 256) {
        float s = sp[n];
        a0 += s * x0[n]; a1 += s * x1[n]; a2 += s * x2[n];
    }
    __shared__ float r[256];
    float acc[3] = {a0, a1, a2};
    for (int d = 0; d < 3; d++) {
        r[tid] = acc[d]; __syncthreads();
        for (int o = 128; o > 0; o >>= 1) { if (tid < o) r[tid] += r[tid+o]; __syncthreads(); }
        if (tid == 0) {
            float invpi = 1.0f / g_pi[b*KK + k];
            g_muxyz[(b*3 + d)*KK + k] = r[0] * invpi;
        }
        __syncthreads();
    }
}

__global__ void invf_kernel(const float* __restrict__ feat) {
    int b = blockIdx.y;
    int n = blockIdx.x * 256 + threadIdx.x;
    float s = 0.0f;
    const float* p = feat + (size_t)b*DD*NPTS + n;
    for (int d = 0; d < DD; d++) { float v = p[(size_t)d*NPTS]; s += v*v; }
    g_invf[b*NPTS + n] = 1.0f / fmaxf(sqrtf(s), 1e-12f);
}

__global__ void invmu_kernel() {
    int b = blockIdx.x, k = threadIdx.x;
    const float4* p = (const float4*)(g_muT + ((size_t)b*KK + k) * DD);
    float s = 0.0f;
    for (int d4 = 0; d4 < DD/4; d4++) {
        float4 v = p[d4];
        s += v.x*v.x + v.y*v.y + v.z*v.z + v.w*v.w;
    }
    g_invmu[b*KK + k] = 1.0f / fmaxf(sqrtf(s), 1e-12f);
}

__global__ void costx_kernel(const float* __restrict__ xyz) {
    int b = blockIdx.y;
    __shared__ float smu[3][64];
    __shared__ float smun[64];
    int tid = threadIdx.x;
    if (tid < 192) smu[tid/64][tid%64] = g_muxyz[b*3*KK + tid];
    __syncthreads();
    if (tid < 64) smun[tid] = smu[0][tid]*smu[0][tid] + smu[1][tid]*smu[1][tid] + smu[2][tid]*smu[2][tid];
    __syncthreads();
    int w = tid >> 5, l = tid & 31;
    int n = blockIdx.x * 8 + w;
    float x0 = xyz[(size_t)(b*3 + 0)*NPTS + n];
    float x1 = xyz[(size_t)(b*3 + 1)*NPTS + n];
    float x2 = xyz[(size_t)(b*3 + 2)*NPTS + n];
    float xn = x0*x0 + x1*x1 + x2*x2;
    float* row = g_costx + ((size_t)b*NPTS + n) * KK;
#pragma unroll
    for (int t = 0; t < 2; t++) {
        int m = l + t*32;
        float d = x0*smu[0][m] + x1*smu[1][m] + x2*smu[2][m];
        row[m] = xn + smun[m] - 2.0f * d;
    }
}

// [b][n][m] -> [b][m][n]
__global__ void transpose_kernel(const float* __restrict__ src, float* __restrict__ dst) {
    __shared__ float t[32][33];
    int b = blockIdx.z;
    int n0 = blockIdx.x * 32, m0 = blockIdx.y * 32;
    int x = threadIdx.x, y = threadIdx.y;
    for (int j = y; j < 32; j += 8)
        t[j][x] = src[((size_t)b*NPTS + n0 + j) * KK + m0 + x];
    __syncthreads();
    for (int j = y; j < 32; j += 8)
        dst[((size_t)b*KK + m0 + j) * NPTS + n0 + x] = t[x][j];
}

// [b][m][n] -> [b][n][m]
__global__ void transposeT_kernel(const float* __restrict__ src, float* __restrict__ dst) {
    __shared__ float t[32][33];
    int b = blockIdx.z;
    int n0 = blockIdx.x * 32, m0 = blockIdx.y * 32;
    int x = threadIdx.x, y = threadIdx.y;
    for (int j = y; j < 32; j += 8)
        t[j][x] = src[((size_t)b*KK + m0 + j) * NPTS + n0 + x];
    __syncthreads();
    for (int j = y; j < 32; j += 8)
        dst[((size_t)b*NPTS + n0 + j) * KK + m0 + x] = t[x][j];
}

__global__ void u_update_kernel() {
    int branch = blockIdx.y;
    const float* C = branch ? g_costf : g_costx;
    const float* v = (branch ? g_v + BB*KK : g_v);
    float* u = (branch ? g_u + BB*NPTS : g_u);
    int r0 = blockIdx.x * 8;
    int b = r0 >> 12;
    __shared__ float vs[64];
    if (threadIdx.x < 64) vs[threadIdx.x] = v[b*KK + threadIdx.x];
    __syncthreads();
    int w = threadIdx.x >> 5, l = threadIdx.x & 31;
    int r = r0 + w;
    const float* Crow = C + (size_t)r * KK;
    float a0 = (vs[l]      - Crow[l])      * INV_EPS;
    float a1 = (vs[l + 32] - Crow[l + 32]) * INV_EPS;
    float mx = fmaxf(a0, a1);
#pragma unroll
    for (int o = 16; o > 0; o >>= 1) mx = fmaxf(mx, __shfl_xor_sync(0xffffffffu, mx, o));
    float s = __expf(a0 - mx) + __expf(a1 - mx);
#pragma unroll
    for (int o = 16; o > 0; o >>= 1) s += __shfl_xor_sync(0xffffffffu, s, o);
    if (l == 0) {
        float epslogp = -SEPS * logf((float)NPTS);
        u[r] = epslogp - SEPS * (mx + logf(s));
    }
}

__global__ void v_update_kernel() {
    int branch = blockIdx.y;
    const float* CT = branch ? g_costfT : g_costxT;
    const float* u = (branch ? g_u + BB*NPTS : g_u);
    float* v = (branch ? g_v + BB*KK : g_v);
    int c = blockIdx.x;
    int b = c >> 6;
    const float* row = CT + (size_t)c * NPTS;
    const float* ub = u + b * NPTS;
    int tid = threadIdx.x;
    float vals[16];
    float mx = -1e30f;
#pragma unroll
    for (int i = 0; i < 16; i++) {
        int n = tid + i * 256;
        vals[i] = (ub[n] - row[n]) * INV_EPS;
        mx = fmaxf(mx, vals[i]);
    }
    __shared__ float r[256];
    r[tid] = mx; __syncthreads();
    for (int o = 128; o > 0; o >>= 1) { if (tid < o) r[tid] = fmaxf(r[tid], r[tid+o]); __syncthreads(); }
    mx = r[0]; __syncthreads();
    float s = 0.0f;
#pragma unroll
    for (int i = 0; i < 16; i++) s += __expf(vals[i] - mx);
    r[tid] = s; __syncthreads();
    for (int o = 128; o > 0; o >>= 1) { if (tid < o) r[tid] += r[tid+o]; __syncthreads(); }
    if (tid == 0) {
        float epslogq = -SEPS * logf((float)KK);
        v[c] = epslogq - SEPS * (mx + logf(r[0]));
    }
}

__global__ void reg_xyz_kernel() {
    int b = blockIdx.x, tid = threadIdx.x;
    float local = 0.0f;
    for (int e = tid; e < KK*KK; e += 256) {
        int m1 = e >> 6, m2 = e & 63;
        float s = 0.0f;
#pragma unroll
        for (int d = 0; d < 3; d++)
            s += g_muxyz[(b*3 + d)*KK + m1] * g_muxyz[(b*3 + d)*KK + m2];
        local += fabsf(s - (m1 == m2 ? 1.0f : 0.0f));
    }
    __shared__ float r[256];
    r[tid] = local; __syncthreads();
    for (int o = 128; o > 0; o >>= 1) { if (tid < o) r[tid] += r[tid+o]; __syncthreads(); }
    if (tid == 0) atomicAdd(&g_acc[2], r[0]);
}

__global__ void reg_fea_kernel() {
    int b = blockIdx.x, tid = threadIdx.x;
    float local = 0.0f;
    for (int e = tid; e < KK*KK; e += 256) {
        int m1 = e >> 6, m2 = e & 63;
        const float4* p1 = (const float4*)(g_muT + ((size_t)b*KK + m1) * DD);
        const float4* p2 = (const float4*)(g_muT + ((size_t)b*KK + m2) * DD);
        float s = 0.0f;
#pragma unroll 4
        for (int d4 = 0; d4 < DD/4; d4++) {
            float4 v1 = p1[d4], v2 = p2[d4];
            s += v1.x*v2.x + v1.y*v2.y + v1.z*v2.z + v1.w*v2.w;
        }
        s *= g_invmu[b*KK + m1] * g_invmu[b*KK + m2];
        local += fabsf(s - (m1 == m2 ? 1.0f : 0.0f));
    }
    __shared__ float r[256];
    r[tid] = local; __syncthreads();
    for (int o = 128; o > 0; o >>= 1) { if (tid < o) r[tid] += r[tid+o]; __syncthreads(); }
    if (tid == 0) atomicAdd(&g_acc[3], r[0]);
}

__global__ void loss_kernel() {
    int branch = blockIdx.y;
    const float* C = branch ? g_costf : g_costx;
    const float* u = (branch ? g_u + BB*NPTS : g_u);
    const float* v = (branch ? g_v + BB*KK : g_v);
    int r0 = blockIdx.x * 8;
    int b = r0 >> 12;
    __shared__ float vs[64];
    if (threadIdx.x < 64) vs[threadIdx.x] = v[b*KK + threadIdx.x];
    __syncthreads();
    int w = threadIdx.x >> 5, l = threadIdx.x & 31;
    int r = r0 + w;
    int n = r & (NPTS - 1);
    const float* Crow = C + (size_t)r * KK;
    float ur = u[r];
    float lsnr = g_lsn[r];
    float acc = 0.0f;
#pragma unroll
    for (int t = 0; t < 2; t++) {
        int m = l + t*32;
        float gma = __expf((ur + vs[m] - Crow[m]) * INV_EPS);
        float lp = g_ls[((size_t)b*KK + m) * NPTS + n] - lsnr;
        acc += gma * lp;
    }
#pragma unroll
    for (int o = 16; o > 0; o >>= 1) acc += __shfl_xor_sync(0xffffffffu, acc, o);
    __shared__ float wsum[8];
    if (l == 0) wsum[w] = acc;
    __syncthreads();
    if (threadIdx.x == 0) {
        float t = 0.0f;
#pragma unroll
        for (int i = 0; i < 8; i++) t += wsum[i];
        atomicAdd(&g_acc[branch], t);
    }
}

__global__ void finalize_kernel(float* __restrict__ out, int out_size) {
    int i = threadIdx.x;
    for (int j = i; j < out_size; j += 32) out[j] = 0.0f;
    __syncwarp();
    if (i == 0) {
        float lx = g_acc[0], lf = g_acc[1], rx = g_acc[2], rf = g_acc[3];
        float loss_xyz = -lx / 8.0f;
        float loss_fea = -lf / 8.0f;
        float reg_fea  = 1e-4f * (rf / (float)(BB*KK*KK));
        float reg_xyz  = 0.001f * 1e-4f * (rx / (float)(BB*KK*KK));
        out[0] = loss_xyz + loss_fea + reg_fea + reg_xyz;
    }
}

// ---------------- launch ----------------
extern "C" void kernel_launch(void* const* d_in, const int* in_sizes, int n_in,
                              void* d_out, int out_size)
{
    const float* feature = (const float*)d_in[0];
    const float* xyz     = (const float*)d_in[1];
    const float* w1      = (const float*)d_in[2];
    const float* b1      = (const float*)d_in[3];
    const float* g1      = (const float*)d_in[4];
    const float* be1     = (const float*)d_in[5];
    const float* w2      = (const float*)d_in[6];
    const float* b2      = (const float*)d_in[7];
    const float* g2      = (const float*)d_in[8];
    const float* be2     = (const float*)d_in[9];
    const float* w3      = (const float*)d_in[10];
    const float* b3      = (const float*)d_in[11];
    float* out = (float*)d_out;

    float* y1; float* y2; float* ls;
    cudaGetSymbolAddress((void**)&y1, g_y1);
    cudaGetSymbolAddress((void**)&y2, g_y2);
    cudaGetSymbolAddress((void**)&ls, g_ls);
    float* sc1; float* sh1; float* sc2; float* sh2;
    cudaGetSymbolAddress((void**)&sc1, g_sc1);
    cudaGetSymbolAddress((void**)&sh1, g_sh1);
    cudaGetSymbolAddress((void**)&sc2, g_sc2);
    cudaGetSymbolAddress((void**)&sh2, g_sh2);
    float* cx; float* cxT; float* cf; float* cfT;
    cudaGetSymbolAddress((void**)&cx,  g_costx);
    cudaGetSymbolAddress((void**)&cxT, g_costxT);
    cudaGetSymbolAddress((void**)&cf,  g_costf);
    cudaGetSymbolAddress((void**)&cfT, g_costfT);
    float* piP; float* muTP; float* invfP; float* invmuP;
    cudaGetSymbolAddress((void**)&piP,    g_pi);
    cudaGetSymbolAddress((void**)&muTP,   g_muT);
    cudaGetSymbolAddress((void**)&invfP,  g_invf);
    cudaGetSymbolAddress((void**)&invmuP, g_invmu);
    __half *fh, *fl, *y1h, *y1l, *y2h, *y2l, *sch, *scl;
    __half *w1h, *w1l, *w2h, *w2l, *w3h, *w3l, *muTh, *muTl;
    cudaGetSymbolAddress((void**)&fh,  g_fh);   cudaGetSymbolAddress((void**)&fl,  g_fl);
    cudaGetSymbolAddress((void**)&y1h, g_y1h);  cudaGetSymbolAddress((void**)&y1l, g_y1l);
    cudaGetSymbolAddress((void**)&y2h, g_y2h);  cudaGetSymbolAddress((void**)&y2l, g_y2l);
    cudaGetSymbolAddress((void**)&sch, g_sch);  cudaGetSymbolAddress((void**)&scl, g_scl);
    cudaGetSymbolAddress((void**)&w1h, g_w1h);  cudaGetSymbolAddress((void**)&w1l, g_w1l);
    cudaGetSymbolAddress((void**)&w2h, g_w2h);  cudaGetSymbolAddress((void**)&w2l, g_w2l);
    cudaGetSymbolAddress((void**)&w3h, g_w3h);  cudaGetSymbolAddress((void**)&w3l, g_w3l);
    cudaGetSymbolAddress((void**)&muTh, g_muTh); cudaGetSymbolAddress((void**)&muTl, g_muTl);

    init_kernel<<<(2*BB*NPTS + 255)/256, 256>>>();

    // operand pre-splits
    {
        size_t n4 = (size_t)BB*DD*NPTS/4;
        convert_pair_kernel<<<(unsigned)((n4 + 255)/256), 256>>>(feature, fh, fl, n4);
    }
    convert_pair_kernel<<<(HH*DD/4 + 255)/256, 256>>>(w1, w1h, w1l, HH*DD/4);
    convert_pair_kernel<<<(HH*HH/4 + 255)/256, 256>>>(w2, w2h, w2l, HH*HH/4);
    convert_pair_kernel<<<(KK*HH/4 + 255)/256, 256>>>(w3, w3h, w3l, KK*HH/4);

    // layer 1
    mma_gemm_kernel<<<dim3(NPTS/128, HH/128, BB), 256>>>(w1h, w1l, fh, fl, b1, y1, DD, HH, 0, 0, nullptr, nullptr);
    bn_stats_kernel<<<HH, 256>>>(y1, g1, be1, sc1, sh1);
    bn_relu_kernel<<<(BB*HH*NPTS/4 + 255)/256, 256>>>(y1, y1h, y1l, sc1, sh1);
    // layer 2
    mma_gemm_kernel<<<dim3(NPTS/128, HH/128, BB), 256>>>(w2h, w2l, y1h, y1l, b2, y2, HH, HH, 0, 0, nullptr, nullptr);
    bn_stats_kernel<<<HH, 256>>>(y2, g2, be2, sc2, sh2);
    bn_relu_kernel<<<(BB*HH*NPTS/4 + 255)/256, 256>>>(y2, y2h, y2l, sc2, sh2);
    // layer 3 (log_score)
    mma_gemm_kernel<<<dim3(NPTS/128, 1, BB), 256>>>(w3h, w3l, y2h, y2l, b3, ls, HH, KK, 0, 0, nullptr, nullptr);

    softmax_kernel<<<dim3(NPTS/256, BB), 256>>>();
    pi_kernel<<<dim3(KK, BB), 256>>>();
    mu_xyz_kernel<<<dim3(KK, BB), 256>>>(xyz);

    mma_nt_kernel<<<dim3(DD/128, 1, BB), 256>>>(sch, scl, fh, fl, piP, muTP, muTh, muTl);
    invf_kernel<<<dim3(NPTS/256, BB), 256>>>(feature);
    invmu_kernel<<<BB, 64>>>();

    mma_gemm_kernel<<<dim3(NPTS/128, 1, BB), 256>>>(muTh, muTl, fh, fl, nullptr, cfT, DD, KK, KK*DD, 1, invfP, invmuP);
    transposeT_kernel<<<dim3(NPTS/32, KK/32, BB), dim3(32, 8)>>>(cfT, cf);

    costx_kernel<<<dim3(NPTS/8, BB), 256>>>(xyz);
    transpose_kernel<<<dim3(NPTS/32, KK/32, BB), dim3(32, 8)>>>(cx, cxT);

    for (int it = 0; it < 25; it++) {
        u_update_kernel<<<dim3(BB*NPTS/8, 2), 256>>>();
        v_update_kernel<<<dim3(BB*KK, 2), 256>>>();
    }

    reg_xyz_kernel<<<BB, 256>>>();
    reg_fea_kernel<<<BB, 256>>>();
    loss_kernel<<<dim3(BB*NPTS/8, 2), 256>>>();
    finalize_kernel<<<1, 32>>>(out, out_size);
}

// round 16
// speedup vs baseline: 1.0452x; 1.0452x over previous
#include <cuda_runtime.h>
#include <cuda_fp16.h>
#include <math.h>
#include <stdint.h>

#define BB   8
#define DD   1024
#define NPTS 4096
#define KK   64
#define HH   512

#define SEPS 1e-3f
#define INV_EPS (1.0f/1e-3f)

// ---------------- scratch (device globals; no allocation) ----------------
static __device__ float g_y1[BB*HH*NPTS];
static __device__ float g_y2[BB*HH*NPTS];
static __device__ float g_ls[BB*KK*NPTS];
static __device__ float g_score[BB*KK*NPTS];
static __device__ float g_lsn[BB*NPTS];
static __device__ float g_pi[BB*KK];
static __device__ float g_sc1[HH], g_sh1[HH], g_sc2[HH], g_sh2[HH];
static __device__ float g_muxyz[BB*3*KK];
static __device__ float g_muT[BB*KK*DD];
static __device__ float g_invf[BB*NPTS];
static __device__ float g_invmu[BB*KK];
static __device__ float g_costx[BB*NPTS*KK];
static __device__ float g_costxT[BB*KK*NPTS];
static __device__ float g_costf[BB*NPTS*KK];
static __device__ float g_costfT[BB*KK*NPTS];
static __device__ float g_u[2*BB*NPTS];
static __device__ float g_v[2*BB*KK];
static __device__ float g_acc[4];

// ================= fp16x3 helpers =================
__device__ __forceinline__ uint32_t split2h(float a, float b) {
    __half2 t = __halves2half2(__float2half_rn(a), __float2half_rn(b));
    return *reinterpret_cast<uint32_t*>(&t);
}
__device__ __forceinline__ uint32_t split2l(float a, float b) {
    __half ha = __float2half_rn(a), hb = __float2half_rn(b);
    float ra = a - __half2float(ha), rb = b - __half2float(hb);
    __half2 t = __halves2half2(__float2half_rn(ra), __float2half_rn(rb));
    return *reinterpret_cast<uint32_t*>(&t);
}

#define MMAH(d, a, b) \
    asm volatile("mma.sync.aligned.m16n8k16.row.col.f32.f16.f16.f32 " \
        "{%0,%1,%2,%3}, {%4,%5,%6,%7}, {%8,%9}, {%0,%1,%2,%3};" \
        : "+f"((d)[0]), "+f"((d)[1]), "+f"((d)[2]), "+f"((d)[3]) \
        : "r"((a).x), "r"((a).y), "r"((a).z), "r"((a).w), "r"((b).x), "r"((b).y))

// ================= main 3xFP16 GEMM (TN), BK=32, dynamic smem =================
// C[b][m][n] = sum_k W[m][k] X[b][k][n]; mode 0: +bias; mode 1: cost-fea epilogue.
// Buffer (words): Ah[0,2048) Al[2048,4096) Bh[4096,6272) Bl[6272,8448)
//  A word: (mtg*2+ks)*128 + slot*4 + r   (slot covers rows g,g+8 / kp tg,tg+4 within sub-chunk ks)
//  B word: kp*136 + n   (kp in [0,16), k = 2kp, 2kp+1)
#define BUFW2 8448
#define GEMM_DSMEM (2 * BUFW2 * 4)   // 67584 bytes

__global__ __launch_bounds__(256, 2)
void mma_gemm_kernel(const float* __restrict__ W, const float* __restrict__ X,
                     const float* __restrict__ bias, float* __restrict__ C,
                     int Kd, int Mtot, int wstride, int mode,
                     const float* __restrict__ invf, const float* __restrict__ invmu)
{
    extern __shared__ uint32_t sm[];
    const int tid = threadIdx.x, wid = tid >> 5, lane = tid & 31;
    const int wm = wid >> 2, wn = wid & 3;
    const int g = lane >> 2, tg = lane & 3;
    const int b = blockIdx.z, n0 = blockIdx.x * 128, m0 = blockIdx.y * 128;
    const float* Wb = W + (size_t)b * wstride;
    const float* Xb = X + (size_t)b * Kd * NPTS;
    float* Cb = C + (size_t)b * Mtot * NPTS;

    float acc[4][4][4];
#pragma unroll
    for (int i = 0; i < 4; i++)
#pragma unroll
        for (int j = 0; j < 4; j++)
#pragma unroll
            for (int r = 0; r < 4; r++) acc[i][j][r] = 0.0f;

    const int CH = Kd / 32;

    // A slot task: mtg=tid>>5, slot s=tid&31 (row g'=s>>2, kpair tg'=s&3), x2 sub-chunks
    const int s_mtg = tid >> 5, s_s = tid & 31;
    const int s_g = s_s >> 2, s_tg = s_s & 3;
    // B task: kp=tid>>5 and kp+8, n4=tid&31
    const int b_kp = tid >> 5, b_n4 = tid & 31;

    float2 aa[2][4];          // [ks][word]
    float4 v0[2], v1[2];      // [half]

    int ms0 = m0 + s_mtg * 16 + s_g;     if (ms0 >= Mtot) ms0 -= Mtot;
    int ms1 = m0 + s_mtg * 16 + s_g + 8; if (ms1 >= Mtot) ms1 -= Mtot;

    auto ldg_regs = [&](int k0) {
#pragma unroll
        for (int ks = 0; ks < 2; ks++) {
            const float* p0 = Wb + (size_t)ms0 * Kd + k0 + ks * 16 + 2 * s_tg;
            const float* p1 = Wb + (size_t)ms1 * Kd + k0 + ks * 16 + 2 * s_tg;
            aa[ks][0] = *(const float2*)(p0);
            aa[ks][1] = *(const float2*)(p1);
            aa[ks][2] = *(const float2*)(p0 + 8);
            aa[ks][3] = *(const float2*)(p1 + 8);
        }
#pragma unroll
        for (int h = 0; h < 2; h++) {
            int kp2 = b_kp + h * 8;
            const float* pb = Xb + (size_t)(k0 + 2 * kp2) * NPTS + n0 + b_n4 * 4;
            v0[h] = *(const float4*)(pb);
            v1[h] = *(const float4*)(pb + (size_t)NPTS);
        }
    };

    auto sts_smem = [&](int buf) {
        uint32_t* Ah = sm + buf * BUFW2;
        uint32_t* Al = Ah + 2048;
        uint32_t* Bh = Ah + 4096;
        uint32_t* Bl = Ah + 6272;
#pragma unroll
        for (int ks = 0; ks < 2; ks++) {
            uint4 hw, lw;
            hw.x = split2h(aa[ks][0].x, aa[ks][0].y); lw.x = split2l(aa[ks][0].x, aa[ks][0].y);
            hw.y = split2h(aa[ks][1].x, aa[ks][1].y); lw.y = split2l(aa[ks][1].x, aa[ks][1].y);
            hw.z = split2h(aa[ks][2].x, aa[ks][2].y); lw.z = split2l(aa[ks][2].x, aa[ks][2].y);
            hw.w = split2h(aa[ks][3].x, aa[ks][3].y); lw.w = split2l(aa[ks][3].x, aa[ks][3].y);
            int o = (s_mtg * 2 + ks) * 128 + s_s * 4;
            *(uint4*)(Ah + o) = hw;
            *(uint4*)(Al + o) = lw;
        }
#pragma unroll
        for (int h = 0; h < 2; h++) {
            int kp2 = b_kp + h * 8;
            uint4 hw, lw;
            hw.x = split2h(v0[h].x, v1[h].x); lw.x = split2l(v0[h].x, v1[h].x);
            hw.y = split2h(v0[h].y, v1[h].y); lw.y = split2l(v0[h].y, v1[h].y);
            hw.z = split2h(v0[h].z, v1[h].z); lw.z = split2l(v0[h].z, v1[h].z);
            hw.w = split2h(v0[h].w, v1[h].w); lw.w = split2l(v0[h].w, v1[h].w);
            int o = kp2 * 136 + b_n4 * 4;
            *(uint4*)(Bh + o) = hw;
            *(uint4*)(Bl + o) = lw;
        }
    };

    ldg_regs(0);
    sts_smem(0);
    __syncthreads();

    for (int c = 0; c < CH; c++) {
        int p = c & 1;
        if (c + 1 < CH) ldg_regs((c + 1) * 32);

        const uint32_t* Ah = sm + p * BUFW2;
        const uint32_t* Al = Ah + 2048;
        const uint32_t* Bh = Ah + 4096;
        const uint32_t* Bl = Ah + 6272;

#pragma unroll
        for (int ks = 0; ks < 2; ks++) {
            uint2 bh[4], bl[4];
#pragma unroll
            for (int nt = 0; nt < 4; nt++) {
                int n = g + (wn * 4 + nt) * 8;
                int r0 = (ks * 8 + tg) * 136 + n;
                int r1 = (ks * 8 + tg + 4) * 136 + n;
                bh[nt].x = Bh[r0];
                bh[nt].y = Bh[r1];
                bl[nt].x = Bl[r0];
                bl[nt].y = Bl[r1];
            }
#pragma unroll
            for (int mt = 0; mt < 4; mt++) {
                int o = ((wm * 4 + mt) * 2 + ks) * 128 + lane * 4;
                uint4 ah = *(const uint4*)(Ah + o);
                uint4 al = *(const uint4*)(Al + o);
#pragma unroll
                for (int nt = 0; nt < 4; nt++) {
                    MMAH(acc[mt][nt], ah, bh[nt]);
                    MMAH(acc[mt][nt], ah, bl[nt]);
                    MMAH(acc[mt][nt], al, bh[nt]);
                }
            }
        }

        if (c + 1 < CH) sts_smem(1 - p);
        __syncthreads();
    }

    // epilogue
#pragma unroll
    for (int mt = 0; mt < 4; mt++) {
        int mrow = m0 + wm * 64 + mt * 16 + g;
#pragma unroll
        for (int half = 0; half < 2; half++) {
            int mg = mrow + half * 8;
            if (mg < Mtot) {
                float* crow = Cb + (size_t)mg * NPTS + n0 + wn * 32 + tg * 2;
                if (mode == 0) {
                    float bi = bias[mg];
#pragma unroll
                    for (int nt = 0; nt < 4; nt++) {
                        float2 vv;
                        vv.x = acc[mt][nt][half * 2 + 0] + bi;
                        vv.y = acc[mt][nt][half * 2 + 1] + bi;
                        *(float2*)(crow + nt * 8) = vv;
                    }
                } else {
                    float im = invmu[b * KK + mg] * 2.0f;
                    const float* fr = invf + b * NPTS + n0 + wn * 32 + tg * 2;
#pragma unroll
                    for (int nt = 0; nt < 4; nt++) {
                        float2 f2 = *(const float2*)(fr + nt * 8);
                        float2 vv;
                        vv.x = 2.0f - acc[mt][nt][half * 2 + 0] * f2.x * im;
                        vv.y = 2.0f - acc[mt][nt][half * 2 + 1] * f2.y * im;
                        *(float2*)(crow + nt * 8) = vv;
                    }
                }
            }
        }
    }
}

// ================= NT fp16x3 GEMM: MuT[b][k][d] (as in R13) ==========
#define NTBUFW 3200

__global__ __launch_bounds__(256, 2)
void mma_nt_kernel(const float* __restrict__ S, const float* __restrict__ F,
                   const float* __restrict__ pi, float* __restrict__ MuT)
{
    __shared__ uint32_t sm[2 * NTBUFW];
    const int tid = threadIdx.x, wid = tid >> 5, lane = tid & 31;
    const int g = lane >> 2, tg = lane & 3;
    const int b = blockIdx.z, n0 = blockIdx.x * 128;
    const float* Sb = S + (size_t)b * KK * NPTS;
    const float* Fb = F + (size_t)b * DD * NPTS;

    float acc[4][2][4];
#pragma unroll
    for (int i = 0; i < 4; i++)
#pragma unroll
        for (int j = 0; j < 2; j++)
#pragma unroll
            for (int r = 0; r < 4; r++) acc[i][j][r] = 0.0f;

    const int s_m = tid >> 2, s_kq = tid & 3;

    float4 a4, b40, b41;
    auto ldg_regs = [&](int k0) {
        a4  = *(const float4*)(Sb + (size_t)s_m * NPTS + k0 + s_kq * 4);
        b40 = *(const float4*)(Fb + (size_t)(n0 + s_m) * NPTS + k0 + s_kq * 4);
        b41 = *(const float4*)(Fb + (size_t)(n0 + s_m + 64) * NPTS + k0 + s_kq * 4);
    };

    auto sts_smem = [&](int buf) {
        uint32_t* Ah = sm + buf * NTBUFW;
        uint32_t* Al = Ah + 512;
        uint32_t* Bh = Ah + 1024;
        uint32_t* Bl = Ah + 2112;
        {
            int kp0 = 2 * s_kq;
            int mt = s_m >> 4;
            int base = mt * 128 + ((s_m & 7) * 4) * 4 + ((s_m >> 3) & 1);
            int o0 = base + (kp0 & 3) * 4 + 2 * (kp0 >> 2);
            int o1 = base + ((kp0 + 1) & 3) * 4 + 2 * ((kp0 + 1) >> 2);
            Ah[o0] = split2h(a4.x, a4.y);  Al[o0] = split2l(a4.x, a4.y);
            Ah[o1] = split2h(a4.z, a4.w);  Al[o1] = split2l(a4.z, a4.w);
        }
        {
            int kp0 = 2 * s_kq;
            int o0 = kp0 * 136 + s_m;
            int o1 = (kp0 + 1) * 136 + s_m;
            Bh[o0] = split2h(b40.x, b40.y);  Bl[o0] = split2l(b40.x, b40.y);
            Bh[o1] = split2h(b40.z, b40.w);  Bl[o1] = split2l(b40.z, b40.w);
            Bh[o0 + 64] = split2h(b41.x, b41.y);  Bl[o0 + 64] = split2l(b41.x, b41.y);
            Bh[o1 + 64] = split2h(b41.z, b41.w);  Bl[o1 + 64] = split2l(b41.z, b41.w);
        }
    };

    ldg_regs(0);
    sts_smem(0);
    __syncthreads();

    const int CH = NPTS / 16;
    for (int c = 0; c < CH; c++) {
        int p = c & 1;
        if (c + 1 < CH) ldg_regs((c + 1) * 16);

        const uint32_t* Ah = sm + p * NTBUFW;
        const uint32_t* Al = Ah + 512;
        const uint32_t* Bh = Ah + 1024;
        const uint32_t* Bl = Ah + 2112;

        uint2 bh[2], bl[2];
#pragma unroll
        for (int nt = 0; nt < 2; nt++) {
            int n = wid * 16 + nt * 8 + g;
            bh[nt].x = Bh[tg * 136 + n];
            bh[nt].y = Bh[(tg + 4) * 136 + n];
            bl[nt].x = Bl[tg * 136 + n];
            bl[nt].y = Bl[(tg + 4) * 136 + n];
        }
#pragma unroll
        for (int mt = 0; mt < 4; mt++) {
            int o = mt * 128 + lane * 4;
            uint4 ah = *(const uint4*)(Ah + o);
            uint4 al = *(const uint4*)(Al + o);
#pragma unroll
            for (int nt = 0; nt < 2; nt++) {
                MMAH(acc[mt][nt], ah, bh[nt]);
                MMAH(acc[mt][nt], ah, bl[nt]);
                MMAH(acc[mt][nt], al, bh[nt]);
            }
        }

        if (c + 1 < CH) sts_smem(1 - p);
        __syncthreads();
    }

#pragma unroll
    for (int mt = 0; mt < 4; mt++) {
#pragma unroll
        for (int half = 0; half < 2; half++) {
            int m = mt * 16 + g + half * 8;
            float ip = 1.0f / pi[b * KK + m];
            float* orow = MuT + ((size_t)b * KK + m) * DD + n0 + wid * 16 + tg * 2;
#pragma unroll
            for (int nt = 0; nt < 2; nt++) {
                float2 vv;
                vv.x = acc[mt][nt][half * 2 + 0] * ip;
                vv.y = acc[mt][nt][half * 2 + 1] * ip;
                *(float2*)(orow + nt * 8) = vv;
            }
        }
    }
}

// ================= remaining kernels (R13) =================
__global__ void init_kernel() {
    int i = blockIdx.x * blockDim.x + threadIdx.x;
    if (i < 2*BB*NPTS) g_u[i] = 0.0f;
    if (i < 2*BB*KK)   g_v[i] = 0.0f;
    if (i < 4)         g_acc[i] = 0.0f;
}

__global__ void bn_stats_kernel(const float* __restrict__ y,
                                const float* __restrict__ g, const float* __restrict__ be,
                                float* __restrict__ sc, float* __restrict__ sh)
{
    int h = blockIdx.x;
    int tid = threadIdx.x;
    float s = 0.0f, s2 = 0.0f;
    for (int b = 0; b < BB; b++) {
        const float* p = y + ((size_t)(b*HH + h)) * NPTS;
        for (int n = tid; n < NPTS; n += 256) { float v = p[n]; s += v; s2 += v*v; }
    }
    __shared__ float r1[256], r2[256];
    r1[tid] = s; r2[tid] = s2; __syncthreads();
    for (int o = 128; o > 0; o >>= 1) {
        if (tid < o) { r1[tid] += r1[tid+o]; r2[tid] += r2[tid+o]; }
        __syncthreads();
    }
    if (tid == 0) {
        float inv = 1.0f / (float)(BB*NPTS);
        float mean = r1[0] * inv;
        float var  = r2[0] * inv - mean*mean;
        float scale = g[h] / sqrtf(var + 1e-5f);
        sc[h] = scale;
        sh[h] = be[h] - mean * scale;
    }
}

__global__ void bn_relu_kernel(float* __restrict__ y,
                               const float* __restrict__ sc, const float* __restrict__ sh)
{
    size_t i4 = (size_t)blockIdx.x * blockDim.x + threadIdx.x;
    size_t total4 = (size_t)BB*HH*NPTS/4;
    if (i4 >= total4) return;
    int h = (int)((i4 / (NPTS/4)) % HH);
    float s = sc[h], t = sh[h];
    float4 v = ((float4*)y)[i4];
    v.x = fmaxf(0.0f, v.x*s + t);
    v.y = fmaxf(0.0f, v.y*s + t);
    v.z = fmaxf(0.0f, v.z*s + t);
    v.w = fmaxf(0.0f, v.w*s + t);
    ((float4*)y)[i4] = v;
}

__global__ void softmax_kernel() {
    int b = blockIdx.y;
    int n = blockIdx.x * 256 + threadIdx.x;
    const float* base = g_ls + (size_t)b*KK*NPTS + n;
    float mx = -1e30f;
#pragma unroll
    for (int k = 0; k < KK; k++) mx = fmaxf(mx, base[(size_t)k*NPTS]);
    float s = 0.0f;
#pragma unroll
    for (int k = 0; k < KK; k++) s += __expf(base[(size_t)k*NPTS] - mx);
    float inv = 1.0f / s;
    float* sb = g_score + (size_t)b*KK*NPTS + n;
#pragma unroll
    for (int k = 0; k < KK; k++) sb[(size_t)k*NPTS] = __expf(base[(size_t)k*NPTS] - mx) * inv;
    g_lsn[b*NPTS + n] = mx + logf(s);
}

__global__ void pi_kernel() {
    int k = blockIdx.x, b = blockIdx.y, tid = threadIdx.x;
    const float* p = g_score + (size_t)(b*KK + k) * NPTS;
    float s = 0.0f;
    for (int n = tid; n < NPTS; n += 256) s += p[n];
    __shared__ float r[256];
    r[tid] = s; __syncthreads();
    for (int o = 128; o > 0; o >>= 1) { if (tid < o) r[tid] += r[tid+o]; __syncthreads(); }
    if (tid == 0) g_pi[b*KK + k] = fmaxf(r[0], 1e-4f);
}

__global__ void mu_xyz_kernel(const float* __restrict__ xyz) {
    int k = blockIdx.x, b = blockIdx.y, tid = threadIdx.x;
    const float* sp = g_score + (size_t)(b*KK + k) * NPTS;
    const float* x0 = xyz + (size_t)(b*3 + 0) * NPTS;
    const float* x1 = xyz + (size_t)(b*3 + 1) * NPTS;
    const float* x2 = xyz + (size_t)(b*3 + 2) * NPTS;
    float a0 = 0, a1 = 0, a2 = 0;
    for (int n = tid; n < NPTS; n += 256) {
        float s = sp[n];
        a0 += s * x0[n]; a1 += s * x1[n]; a2 += s * x2[n];
    }
    __shared__ float r[256];
    float acc[3] = {a0, a1, a2};
    for (int d = 0; d < 3; d++) {
        r[tid] = acc[d]; __syncthreads();
        for (int o = 128; o > 0; o >>= 1) { if (tid < o) r[tid] += r[tid+o]; __syncthreads(); }
        if (tid == 0) {
            float invpi = 1.0f / g_pi[b*KK + k];
            g_muxyz[(b*3 + d)*KK + k] = r[0] * invpi;
        }
        __syncthreads();
    }
}

__global__ void invf_kernel(const float* __restrict__ feat) {
    int b = blockIdx.y;
    int n = blockIdx.x * 256 + threadIdx.x;
    float s = 0.0f;
    const float* p = feat + (size_t)b*DD*NPTS + n;
    for (int d = 0; d < DD; d++) { float v = p[(size_t)d*NPTS]; s += v*v; }
    g_invf[b*NPTS + n] = 1.0f / fmaxf(sqrtf(s), 1e-12f);
}

__global__ void invmu_kernel() {
    int b = blockIdx.x, k = threadIdx.x;
    const float4* p = (const float4*)(g_muT + ((size_t)b*KK + k) * DD);
    float s = 0.0f;
    for (int d4 = 0; d4 < DD/4; d4++) {
        float4 v = p[d4];
        s += v.x*v.x + v.y*v.y + v.z*v.z + v.w*v.w;
    }
    g_invmu[b*KK + k] = 1.0f / fmaxf(sqrtf(s), 1e-12f);
}

__global__ void costx_kernel(const float* __restrict__ xyz) {
    int b = blockIdx.y;
    __shared__ float smu[3][64];
    __shared__ float smun[64];
    int tid = threadIdx.x;
    if (tid < 192) smu[tid/64][tid%64] = g_muxyz[b*3*KK + tid];
    __syncthreads();
    if (tid < 64) smun[tid] = smu[0][tid]*smu[0][tid] + smu[1][tid]*smu[1][tid] + smu[2][tid]*smu[2][tid];
    __syncthreads();
    int w = tid >> 5, l = tid & 31;
    int n = blockIdx.x * 8 + w;
    float x0 = xyz[(size_t)(b*3 + 0)*NPTS + n];
    float x1 = xyz[(size_t)(b*3 + 1)*NPTS + n];
    float x2 = xyz[(size_t)(b*3 + 2)*NPTS + n];
    float xn = x0*x0 + x1*x1 + x2*x2;
    float* row = g_costx + ((size_t)b*NPTS + n) * KK;
#pragma unroll
    for (int t = 0; t < 2; t++) {
        int m = l + t*32;
        float d = x0*smu[0][m] + x1*smu[1][m] + x2*smu[2][m];
        row[m] = xn + smun[m] - 2.0f * d;
    }
}

// [b][n][m] -> [b][m][n]
__global__ void transpose_kernel(const float* __restrict__ src, float* __restrict__ dst) {
    __shared__ float t[32][33];
    int b = blockIdx.z;
    int n0 = blockIdx.x * 32, m0 = blockIdx.y * 32;
    int x = threadIdx.x, y = threadIdx.y;
    for (int j = y; j < 32; j += 8)
        t[j][x] = src[((size_t)b*NPTS + n0 + j) * KK + m0 + x];
    __syncthreads();
    for (int j = y; j < 32; j += 8)
        dst[((size_t)b*KK + m0 + j) * NPTS + n0 + x] = t[x][j];
}

// [b][m][n] -> [b][n][m]
__global__ void transposeT_kernel(const float* __restrict__ src, float* __restrict__ dst) {
    __shared__ float t[32][33];
    int b = blockIdx.z;
    int n0 = blockIdx.x * 32, m0 = blockIdx.y * 32;
    int x = threadIdx.x, y = threadIdx.y;
    for (int j = y; j < 32; j += 8)
        t[j][x] = src[((size_t)b*KK + m0 + j) * NPTS + n0 + x];
    __syncthreads();
    for (int j = y; j < 32; j += 8)
        dst[((size_t)b*NPTS + n0 + j) * KK + m0 + x] = t[x][j];
}

__global__ void u_update_kernel() {
    int branch = blockIdx.y;
    const float* C = branch ? g_costf : g_costx;
    const float* v = (branch ? g_v + BB*KK : g_v);
    float* u = (branch ? g_u + BB*NPTS : g_u);
    int r0 = blockIdx.x * 8;
    int b = r0 >> 12;
    __shared__ float vs[64];
    if (threadIdx.x < 64) vs[threadIdx.x] = v[b*KK + threadIdx.x];
    __syncthreads();
    int w = threadIdx.x >> 5, l = threadIdx.x & 31;
    int r = r0 + w;
    const float* Crow = C + (size_t)r * KK;
    float a0 = (vs[l]      - Crow[l])      * INV_EPS;
    float a1 = (vs[l + 32] - Crow[l + 32]) * INV_EPS;
    float mx = fmaxf(a0, a1);
#pragma unroll
    for (int o = 16; o > 0; o >>= 1) mx = fmaxf(mx, __shfl_xor_sync(0xffffffffu, mx, o));
    float s = __expf(a0 - mx) + __expf(a1 - mx);
#pragma unroll
    for (int o = 16; o > 0; o >>= 1) s += __shfl_xor_sync(0xffffffffu, s, o);
    if (l == 0) {
        float epslogp = -SEPS * logf((float)NPTS);
        u[r] = epslogp - SEPS * (mx + logf(s));
    }
}

__global__ void v_update_kernel() {
    int branch = blockIdx.y;
    const float* CT = branch ? g_costfT : g_costxT;
    const float* u = (branch ? g_u + BB*NPTS : g_u);
    float* v = (branch ? g_v + BB*KK : g_v);
    int c = blockIdx.x;
    int b = c >> 6;
    const float* row = CT + (size_t)c * NPTS;
    const float* ub = u + b * NPTS;
    int tid = threadIdx.x;
    float vals[16];
    float mx = -1e30f;
#pragma unroll
    for (int i = 0; i < 16; i++) {
        int n = tid + i * 256;
        vals[i] = (ub[n] - row[n]) * INV_EPS;
        mx = fmaxf(mx, vals[i]);
    }
    __shared__ float r[256];
    r[tid] = mx; __syncthreads();
    for (int o = 128; o > 0; o >>= 1) { if (tid < o) r[tid] = fmaxf(r[tid], r[tid+o]); __syncthreads(); }
    mx = r[0]; __syncthreads();
    float s = 0.0f;
#pragma unroll
    for (int i = 0; i < 16; i++) s += __expf(vals[i] - mx);
    r[tid] = s; __syncthreads();
    for (int o = 128; o > 0; o >>= 1) { if (tid < o) r[tid] += r[tid+o]; __syncthreads(); }
    if (tid == 0) {
        float epslogq = -SEPS * logf((float)KK);
        v[c] = epslogq - SEPS * (mx + logf(r[0]));
    }
}

__global__ void reg_xyz_kernel() {
    int b = blockIdx.x, tid = threadIdx.x;
    float local = 0.0f;
    for (int e = tid; e < KK*KK; e += 256) {
        int m1 = e >> 6, m2 = e & 63;
        float s = 0.0f;
#pragma unroll
        for (int d = 0; d < 3; d++)
            s += g_muxyz[(b*3 + d)*KK + m1] * g_muxyz[(b*3 + d)*KK + m2];
        local += fabsf(s - (m1 == m2 ? 1.0f : 0.0f));
    }
    __shared__ float r[256];
    r[tid] = local; __syncthreads();
    for (int o = 128; o > 0; o >>= 1) { if (tid < o) r[tid] += r[tid+o]; __syncthreads(); }
    if (tid == 0) atomicAdd(&g_acc[2], r[0]);
}

__global__ void reg_fea_kernel() {
    int b = blockIdx.x, tid = threadIdx.x;
    float local = 0.0f;
    for (int e = tid; e < KK*KK; e += 256) {
        int m1 = e >> 6, m2 = e & 63;
        const float4* p1 = (const float4*)(g_muT + ((size_t)b*KK + m1) * DD);
        const float4* p2 = (const float4*)(g_muT + ((size_t)b*KK + m2) * DD);
        float s = 0.0f;
#pragma unroll 4
        for (int d4 = 0; d4 < DD/4; d4++) {
            float4 v1 = p1[d4], v2 = p2[d4];
            s += v1.x*v2.x + v1.y*v2.y + v1.z*v2.z + v1.w*v2.w;
        }
        s *= g_invmu[b*KK + m1] * g_invmu[b*KK + m2];
        local += fabsf(s - (m1 == m2 ? 1.0f : 0.0f));
    }
    __shared__ float r[256];
    r[tid] = local; __syncthreads();
    for (int o = 128; o > 0; o >>= 1) { if (tid < o) r[tid] += r[tid+o]; __syncthreads(); }
    if (tid == 0) atomicAdd(&g_acc[3], r[0]);
}

__global__ void loss_kernel() {
    int branch = blockIdx.y;
    const float* C = branch ? g_costf : g_costx;
    const float* u = (branch ? g_u + BB*NPTS : g_u);
    const float* v = (branch ? g_v + BB*KK : g_v);
    int r0 = blockIdx.x * 8;
    int b = r0 >> 12;
    __shared__ float vs[64];
    if (threadIdx.x < 64) vs[threadIdx.x] = v[b*KK + threadIdx.x];
    __syncthreads();
    int w = threadIdx.x >> 5, l = threadIdx.x & 31;
    int r = r0 + w;
    int n = r & (NPTS - 1);
    const float* Crow = C + (size_t)r * KK;
    float ur = u[r];
    float lsnr = g_lsn[r];
    float acc = 0.0f;
#pragma unroll
    for (int t = 0; t < 2; t++) {
        int m = l + t*32;
        float gma = __expf((ur + vs[m] - Crow[m]) * INV_EPS);
        float lp = g_ls[((size_t)b*KK + m) * NPTS + n] - lsnr;
        acc += gma * lp;
    }
#pragma unroll
    for (int o = 16; o > 0; o >>= 1) acc += __shfl_xor_sync(0xffffffffu, acc, o);
    __shared__ float wsum[8];
    if (l == 0) wsum[w] = acc;
    __syncthreads();
    if (threadIdx.x == 0) {
        float t = 0.0f;
#pragma unroll
        for (int i = 0; i < 8; i++) t += wsum[i];
        atomicAdd(&g_acc[branch], t);
    }
}

__global__ void finalize_kernel(float* __restrict__ out, int out_size) {
    int i = threadIdx.x;
    for (int j = i; j < out_size; j += 32) out[j] = 0.0f;
    __syncwarp();
    if (i == 0) {
        float lx = g_acc[0], lf = g_acc[1], rx = g_acc[2], rf = g_acc[3];
        float loss_xyz = -lx / 8.0f;
        float loss_fea = -lf / 8.0f;
        float reg_fea  = 1e-4f * (rf / (float)(BB*KK*KK));
        float reg_xyz  = 0.001f * 1e-4f * (rx / (float)(BB*KK*KK));
        out[0] = loss_xyz + loss_fea + reg_fea + reg_xyz;
    }
}

// ---------------- launch ----------------
extern "C" void kernel_launch(void* const* d_in, const int* in_sizes, int n_in,
                              void* d_out, int out_size)
{
    const float* feature = (const float*)d_in[0];
    const float* xyz     = (const float*)d_in[1];
    const float* w1      = (const float*)d_in[2];
    const float* b1      = (const float*)d_in[3];
    const float* g1      = (const float*)d_in[4];
    const float* be1     = (const float*)d_in[5];
    const float* w2      = (const float*)d_in[6];
    const float* b2      = (const float*)d_in[7];
    const float* g2      = (const float*)d_in[8];
    const float* be2     = (const float*)d_in[9];
    const float* w3      = (const float*)d_in[10];
    const float* b3      = (const float*)d_in[11];
    float* out = (float*)d_out;

    float* y1; float* y2; float* ls;
    cudaGetSymbolAddress((void**)&y1, g_y1);
    cudaGetSymbolAddress((void**)&y2, g_y2);
    cudaGetSymbolAddress((void**)&ls, g_ls);
    float* sc1; float* sh1; float* sc2; float* sh2;
    cudaGetSymbolAddress((void**)&sc1, g_sc1);
    cudaGetSymbolAddress((void**)&sh1, g_sh1);
    cudaGetSymbolAddress((void**)&sc2, g_sc2);
    cudaGetSymbolAddress((void**)&sh2, g_sh2);
    float* cx; float* cxT; float* cf; float* cfT;
    cudaGetSymbolAddress((void**)&cx,  g_costx);
    cudaGetSymbolAddress((void**)&cxT, g_costxT);
    cudaGetSymbolAddress((void**)&cf,  g_costf);
    cudaGetSymbolAddress((void**)&cfT, g_costfT);
    float* scoreP; float* piP; float* muTP; float* invfP; float* invmuP;
    cudaGetSymbolAddress((void**)&scoreP, g_score);
    cudaGetSymbolAddress((void**)&piP,    g_pi);
    cudaGetSymbolAddress((void**)&muTP,   g_muT);
    cudaGetSymbolAddress((void**)&invfP,  g_invf);
    cudaGetSymbolAddress((void**)&invmuP, g_invmu);

    static int smem_set = 0;
    if (!smem_set) {
        cudaFuncSetAttribute(mma_gemm_kernel, cudaFuncAttributeMaxDynamicSharedMemorySize, GEMM_DSMEM);
        smem_set = 1;
    }

    init_kernel<<<(2*BB*NPTS + 255)/256, 256>>>();

    // layer 1
    mma_gemm_kernel<<<dim3(NPTS/128, HH/128, BB), 256, GEMM_DSMEM>>>(w1, feature, b1, y1, DD, HH, 0, 0, nullptr, nullptr);
    bn_stats_kernel<<<HH, 256>>>(y1, g1, be1, sc1, sh1);
    bn_relu_kernel<<<(BB*HH*NPTS/4 + 255)/256, 256>>>(y1, sc1, sh1);
    // layer 2
    mma_gemm_kernel<<<dim3(NPTS/128, HH/128, BB), 256, GEMM_DSMEM>>>(w2, y1, b2, y2, HH, HH, 0, 0, nullptr, nullptr);
    bn_stats_kernel<<<HH, 256>>>(y2, g2, be2, sc2, sh2);
    bn_relu_kernel<<<(BB*HH*NPTS/4 + 255)/256, 256>>>(y2, sc2, sh2);
    // layer 3 (log_score)
    mma_gemm_kernel<<<dim3(NPTS/128, 1, BB), 256, GEMM_DSMEM>>>(w3, y2, b3, ls, HH, KK, 0, 0, nullptr, nullptr);

    softmax_kernel<<<dim3(NPTS/256, BB), 256>>>();
    pi_kernel<<<dim3(KK, BB), 256>>>();
    mu_xyz_kernel<<<dim3(KK, BB), 256>>>(xyz);

    mma_nt_kernel<<<dim3(DD/128, 1, BB), 256>>>(scoreP, feature, piP, muTP);
    invf_kernel<<<dim3(NPTS/256, BB), 256>>>(feature);
    invmu_kernel<<<BB, 64>>>();

    mma_gemm_kernel<<<dim3(NPTS/128, 1, BB), 256, GEMM_DSMEM>>>(muTP, feature, nullptr, cfT, DD, KK, KK*DD, 1, invfP, invmuP);
    transposeT_kernel<<<dim3(NPTS/32, KK/32, BB), dim3(32, 8)>>>(cfT, cf);

    costx_kernel<<<dim3(NPTS/8, BB), 256>>>(xyz);
    transpose_kernel<<<dim3(NPTS/32, KK/32, BB), dim3(32, 8)>>>(cx, cxT);

    for (int it = 0; it < 25; it++) {
        u_update_kernel<<<dim3(BB*NPTS/8, 2), 256>>>();
        v_update_kernel<<<dim3(BB*KK, 2), 256>>>();
    }

    reg_xyz_kernel<<<BB, 256>>>();
    reg_fea_kernel<<<BB, 256>>>();
    loss_kernel<<<dim3(BB*NPTS/8, 2), 256>>>();
    finalize_kernel<<<1, 32>>>(out, out_size);
}

// round 17
// speedup vs baseline: 1.0611x; 1.0152x over previous
#include <cuda_runtime.h>
#include <cuda_fp16.h>
#include <math.h>
#include <stdint.h>

#define BB   8
#define DD   1024
#define NPTS 4096
#define KK   64
#define HH   512

#define SEPS 1e-3f
#define INV_EPS (1.0f/1e-3f)

// ---------------- scratch (device globals; no allocation) ----------------
static __device__ float g_y1[BB*HH*NPTS];
static __device__ float g_y2[BB*HH*NPTS];
static __device__ float g_ls[BB*KK*NPTS];
static __device__ float g_score[BB*KK*NPTS];
static __device__ float g_lsn[BB*NPTS];
static __device__ float g_pi[BB*KK];
static __device__ float g_sc1[HH], g_sh1[HH], g_sc2[HH], g_sh2[HH];
static __device__ float g_muxyz[BB*3*KK];
static __device__ float g_muT[BB*KK*DD];
static __device__ float g_invf[BB*NPTS];
static __device__ float g_invmu[BB*KK];
static __device__ float g_costx[BB*NPTS*KK];
static __device__ float g_costxT[BB*KK*NPTS];
static __device__ float g_costf[BB*NPTS*KK];
static __device__ float g_costfT[BB*KK*NPTS];
static __device__ float g_u[2*BB*NPTS];
static __device__ float g_v[2*BB*KK];
static __device__ float g_acc[4];

// ================= fp16x3 helpers =================
__device__ __forceinline__ uint32_t split2h(float a, float b) {
    __half2 t = __halves2half2(__float2half_rn(a), __float2half_rn(b));
    return *reinterpret_cast<uint32_t*>(&t);
}
__device__ __forceinline__ uint32_t split2l(float a, float b) {
    __half ha = __float2half_rn(a), hb = __float2half_rn(b);
    float ra = a - __half2float(ha), rb = b - __half2float(hb);
    __half2 t = __halves2half2(__float2half_rn(ra), __float2half_rn(rb));
    return *reinterpret_cast<uint32_t*>(&t);
}

#define MMAH(d, a, b) \
    asm volatile("mma.sync.aligned.m16n8k16.row.col.f32.f16.f16.f32 " \
        "{%0,%1,%2,%3}, {%4,%5,%6,%7}, {%8,%9}, {%0,%1,%2,%3};" \
        : "+f"((d)[0]), "+f"((d)[1]), "+f"((d)[2]), "+f"((d)[3]) \
        : "r"((a).x), "r"((a).y), "r"((a).z), "r"((a).w), "r"((b).x), "r"((b).y))

// ================= main 3xFP16 GEMM (TN), BK=16, product-major MMA order ========
// C[b][m][n] = sum_k W[m][k] X[b][k][n]; mode 0: +bias; mode 1: cost-fea epilogue.
#define BUFW 4224   // Ah[0,1024) Al[1024,2048) Bh[2048,3136) Bl[3136,4224)

__global__ __launch_bounds__(256, 2)
void mma_gemm_kernel(const float* __restrict__ W, const float* __restrict__ X,
                     const float* __restrict__ bias, float* __restrict__ C,
                     int Kd, int Mtot, int wstride, int mode,
                     const float* __restrict__ invf, const float* __restrict__ invmu)
{
    __shared__ uint32_t sm[2 * BUFW];
    const int tid = threadIdx.x, wid = tid >> 5, lane = tid & 31;
    const int wm = wid >> 2, wn = wid & 3;
    const int g = lane >> 2, tg = lane & 3;
    const int b = blockIdx.z, n0 = blockIdx.x * 128, m0 = blockIdx.y * 128;
    const float* Wb = W + (size_t)b * wstride;
    const float* Xb = X + (size_t)b * Kd * NPTS;
    float* Cb = C + (size_t)b * Mtot * NPTS;

    float acc[4][4][4];
#pragma unroll
    for (int i = 0; i < 4; i++)
#pragma unroll
        for (int j = 0; j < 4; j++)
#pragma unroll
            for (int r = 0; r < 4; r++) acc[i][j][r] = 0.0f;

    const int CH = Kd / 16;

    const int a_mtg = tid >> 5, a_tt = tid & 31;
    const int a_row = a_mtg * 16 + (a_tt >> 2);
    const int a_tg = a_tt & 3;
    const int b_kpg = tid >> 5, b_nq = tid & 31;

    float2 a00, a01, a10, a11;
    float4 v0, v1;

    auto ldg_regs = [&](int k0) {
        int ms0 = m0 + a_row;     if (ms0 >= Mtot) ms0 -= Mtot;
        int ms1 = m0 + a_row + 8; if (ms1 >= Mtot) ms1 -= Mtot;
        const float* p0 = Wb + (size_t)ms0 * Kd + k0 + 2 * a_tg;
        const float* p1 = Wb + (size_t)ms1 * Kd + k0 + 2 * a_tg;
        a00 = *(const float2*)(p0);
        a01 = *(const float2*)(p0 + 8);
        a10 = *(const float2*)(p1);
        a11 = *(const float2*)(p1 + 8);
        const float* pb = Xb + (size_t)(k0 + 2 * b_kpg) * NPTS + n0 + b_nq * 4;
        v0 = *(const float4*)(pb);
        v1 = *(const float4*)(pb + (size_t)NPTS);
    };

    auto sts_smem = [&](int buf) {
        uint32_t* Ah = sm + buf * BUFW;
        uint32_t* Al = Ah + 1024;
        uint32_t* Bh = Ah + 2048;
        uint32_t* Bl = Ah + 3136;
        {
            uint4 hw, lw;
            hw.x = split2h(a00.x, a00.y); lw.x = split2l(a00.x, a00.y);
            hw.y = split2h(a10.x, a10.y); lw.y = split2l(a10.x, a10.y);
            hw.z = split2h(a01.x, a01.y); lw.z = split2l(a01.x, a01.y);
            hw.w = split2h(a11.x, a11.y); lw.w = split2l(a11.x, a11.y);
            int o = a_mtg * 128 + a_tt * 4;
            *(uint4*)(Ah + o) = hw;
            *(uint4*)(Al + o) = lw;
        }
        {
            uint4 hw, lw;
            hw.x = split2h(v0.x, v1.x); lw.x = split2l(v0.x, v1.x);
            hw.y = split2h(v0.y, v1.y); lw.y = split2l(v0.y, v1.y);
            hw.z = split2h(v0.z, v1.z); lw.z = split2l(v0.z, v1.z);
            hw.w = split2h(v0.w, v1.w); lw.w = split2l(v0.w, v1.w);
            int o = b_kpg * 136 + b_nq * 4;
            *(uint4*)(Bh + o) = hw;
            *(uint4*)(Bl + o) = lw;
        }
    };

    ldg_regs(0);
    sts_smem(0);
    __syncthreads();

    for (int c = 0; c < CH; c++) {
        int p = c & 1;
        if (c + 1 < CH) ldg_regs((c + 1) * 16);

        const uint32_t* Ah = sm + p * BUFW;
        const uint32_t* Al = Ah + 1024;
        const uint32_t* Bh = Ah + 2048;
        const uint32_t* Bl = Ah + 3136;

        uint4 ah[4];
        uint2 bh[4], bl[4];
#pragma unroll
        for (int mt = 0; mt < 4; mt++)
            ah[mt] = *(const uint4*)(Ah + (wm * 4 + mt) * 128 + lane * 4);
#pragma unroll
        for (int nt = 0; nt < 4; nt++) {
            int n = g + (wn * 4 + nt) * 8;
            bh[nt].x = Bh[tg * 136 + n];
            bh[nt].y = Bh[(tg + 4) * 136 + n];
            bl[nt].x = Bl[tg * 136 + n];
            bl[nt].y = Bl[(tg + 4) * 136 + n];
        }
        // pass 1: hi*hi  (16 independent accumulators)
#pragma unroll
        for (int mt = 0; mt < 4; mt++)
#pragma unroll
            for (int nt = 0; nt < 4; nt++)
                MMAH(acc[mt][nt], ah[mt], bh[nt]);
        // pass 2: hi*lo
#pragma unroll
        for (int mt = 0; mt < 4; mt++)
#pragma unroll
            for (int nt = 0; nt < 4; nt++)
                MMAH(acc[mt][nt], ah[mt], bl[nt]);
        // pass 3: lo*hi (al loaded per-mt to cap registers)
#pragma unroll
        for (int mt = 0; mt < 4; mt++) {
            uint4 al = *(const uint4*)(Al + (wm * 4 + mt) * 128 + lane * 4);
#pragma unroll
            for (int nt = 0; nt < 4; nt++)
                MMAH(acc[mt][nt], al, bh[nt]);
        }

        if (c + 1 < CH) sts_smem(1 - p);
        __syncthreads();
    }

    // epilogue
#pragma unroll
    for (int mt = 0; mt < 4; mt++) {
        int mrow = m0 + wm * 64 + mt * 16 + g;
#pragma unroll
        for (int half = 0; half < 2; half++) {
            int mg = mrow + half * 8;
            if (mg < Mtot) {
                float* crow = Cb + (size_t)mg * NPTS + n0 + wn * 32 + tg * 2;
                if (mode == 0) {
                    float bi = bias[mg];
#pragma unroll
                    for (int nt = 0; nt < 4; nt++) {
                        float2 vv;
                        vv.x = acc[mt][nt][half * 2 + 0] + bi;
                        vv.y = acc[mt][nt][half * 2 + 1] + bi;
                        *(float2*)(crow + nt * 8) = vv;
                    }
                } else {
                    float im = invmu[b * KK + mg] * 2.0f;
                    const float* fr = invf + b * NPTS + n0 + wn * 32 + tg * 2;
#pragma unroll
                    for (int nt = 0; nt < 4; nt++) {
                        float2 f2 = *(const float2*)(fr + nt * 8);
                        float2 vv;
                        vv.x = 2.0f - acc[mt][nt][half * 2 + 0] * f2.x * im;
                        vv.y = 2.0f - acc[mt][nt][half * 2 + 1] * f2.y * im;
                        *(float2*)(crow + nt * 8) = vv;
                    }
                }
            }
        }
    }
}

// ================= NT fp16x3 GEMM: MuT[b][k][d], product-major order ==========
#define NTBUFW 3200

__global__ __launch_bounds__(256, 2)
void mma_nt_kernel(const float* __restrict__ S, const float* __restrict__ F,
                   const float* __restrict__ pi, float* __restrict__ MuT)
{
    __shared__ uint32_t sm[2 * NTBUFW];
    const int tid = threadIdx.x, wid = tid >> 5, lane = tid & 31;
    const int g = lane >> 2, tg = lane & 3;
    const int b = blockIdx.z, n0 = blockIdx.x * 128;
    const float* Sb = S + (size_t)b * KK * NPTS;
    const float* Fb = F + (size_t)b * DD * NPTS;

    float acc[4][2][4];
#pragma unroll
    for (int i = 0; i < 4; i++)
#pragma unroll
        for (int j = 0; j < 2; j++)
#pragma unroll
            for (int r = 0; r < 4; r++) acc[i][j][r] = 0.0f;

    const int s_m = tid >> 2, s_kq = tid & 3;

    float4 a4, b40, b41;
    auto ldg_regs = [&](int k0) {
        a4  = *(const float4*)(Sb + (size_t)s_m * NPTS + k0 + s_kq * 4);
        b40 = *(const float4*)(Fb + (size_t)(n0 + s_m) * NPTS + k0 + s_kq * 4);
        b41 = *(const float4*)(Fb + (size_t)(n0 + s_m + 64) * NPTS + k0 + s_kq * 4);
    };

    auto sts_smem = [&](int buf) {
        uint32_t* Ah = sm + buf * NTBUFW;
        uint32_t* Al = Ah + 512;
        uint32_t* Bh = Ah + 1024;
        uint32_t* Bl = Ah + 2112;
        {
            int kp0 = 2 * s_kq;
            int mt = s_m >> 4;
            int base = mt * 128 + ((s_m & 7) * 4) * 4 + ((s_m >> 3) & 1);
            int o0 = base + (kp0 & 3) * 4 + 2 * (kp0 >> 2);
            int o1 = base + ((kp0 + 1) & 3) * 4 + 2 * ((kp0 + 1) >> 2);
            Ah[o0] = split2h(a4.x, a4.y);  Al[o0] = split2l(a4.x, a4.y);
            Ah[o1] = split2h(a4.z, a4.w);  Al[o1] = split2l(a4.z, a4.w);
        }
        {
            int kp0 = 2 * s_kq;
            int o0 = kp0 * 136 + s_m;
            int o1 = (kp0 + 1) * 136 + s_m;
            Bh[o0] = split2h(b40.x, b40.y);  Bl[o0] = split2l(b40.x, b40.y);
            Bh[o1] = split2h(b40.z, b40.w);  Bl[o1] = split2l(b40.z, b40.w);
            Bh[o0 + 64] = split2h(b41.x, b41.y);  Bl[o0 + 64] = split2l(b41.x, b41.y);
            Bh[o1 + 64] = split2h(b41.z, b41.w);  Bl[o1 + 64] = split2l(b41.z, b41.w);
        }
    };

    ldg_regs(0);
    sts_smem(0);
    __syncthreads();

    const int CH = NPTS / 16;
    for (int c = 0; c < CH; c++) {
        int p = c & 1;
        if (c + 1 < CH) ldg_regs((c + 1) * 16);

        const uint32_t* Ah = sm + p * NTBUFW;
        const uint32_t* Al = Ah + 512;
        const uint32_t* Bh = Ah + 1024;
        const uint32_t* Bl = Ah + 2112;

        uint4 ah[4];
        uint2 bh[2], bl[2];
#pragma unroll
        for (int mt = 0; mt < 4; mt++)
            ah[mt] = *(const uint4*)(Ah + mt * 128 + lane * 4);
#pragma unroll
        for (int nt = 0; nt < 2; nt++) {
            int n = wid * 16 + nt * 8 + g;
            bh[nt].x = Bh[tg * 136 + n];
            bh[nt].y = Bh[(tg + 4) * 136 + n];
            bl[nt].x = Bl[tg * 136 + n];
            bl[nt].y = Bl[(tg + 4) * 136 + n];
        }
#pragma unroll
        for (int mt = 0; mt < 4; mt++)
#pragma unroll
            for (int nt = 0; nt < 2; nt++)
                MMAH(acc[mt][nt], ah[mt], bh[nt]);
#pragma unroll
        for (int mt = 0; mt < 4; mt++)
#pragma unroll
            for (int nt = 0; nt < 2; nt++)
                MMAH(acc[mt][nt], ah[mt], bl[nt]);
#pragma unroll
        for (int mt = 0; mt < 4; mt++) {
            uint4 al = *(const uint4*)(Al + mt * 128 + lane * 4);
#pragma unroll
            for (int nt = 0; nt < 2; nt++)
                MMAH(acc[mt][nt], al, bh[nt]);
        }

        if (c + 1 < CH) sts_smem(1 - p);
        __syncthreads();
    }

#pragma unroll
    for (int mt = 0; mt < 4; mt++) {
#pragma unroll
        for (int half = 0; half < 2; half++) {
            int m = mt * 16 + g + half * 8;
            float ip = 1.0f / pi[b * KK + m];
            float* orow = MuT + ((size_t)b * KK + m) * DD + n0 + wid * 16 + tg * 2;
#pragma unroll
            for (int nt = 0; nt < 2; nt++) {
                float2 vv;
                vv.x = acc[mt][nt][half * 2 + 0] * ip;
                vv.y = acc[mt][nt][half * 2 + 1] * ip;
                *(float2*)(orow + nt * 8) = vv;
            }
        }
    }
}

// ================= remaining kernels =================
__global__ void init_kernel() {
    int i = blockIdx.x * blockDim.x + threadIdx.x;
    if (i < 2*BB*NPTS) g_u[i] = 0.0f;
    if (i < 2*BB*KK)   g_v[i] = 0.0f;
    if (i < 4)         g_acc[i] = 0.0f;
}

__global__ void bn_stats_kernel(const float* __restrict__ y,
                                const float* __restrict__ g, const float* __restrict__ be,
                                float* __restrict__ sc, float* __restrict__ sh)
{
    int h = blockIdx.x;
    int tid = threadIdx.x;
    float s = 0.0f, s2 = 0.0f;
    for (int b = 0; b < BB; b++) {
        const float* p = y + ((size_t)(b*HH + h)) * NPTS;
        for (int n = tid; n < NPTS; n += 256) { float v = p[n]; s += v; s2 += v*v; }
    }
    __shared__ float r1[256], r2[256];
    r1[tid] = s; r2[tid] = s2; __syncthreads();
    for (int o = 128; o > 0; o >>= 1) {
        if (tid < o) { r1[tid] += r1[tid+o]; r2[tid] += r2[tid+o]; }
        __syncthreads();
    }
    if (tid == 0) {
        float inv = 1.0f / (float)(BB*NPTS);
        float mean = r1[0] * inv;
        float var  = r2[0] * inv - mean*mean;
        float scale = g[h] / sqrtf(var + 1e-5f);
        sc[h] = scale;
        sh[h] = be[h] - mean * scale;
    }
}

__global__ void bn_relu_kernel(float* __restrict__ y,
                               const float* __restrict__ sc, const float* __restrict__ sh)
{
    size_t i4 = (size_t)blockIdx.x * blockDim.x + threadIdx.x;
    size_t total4 = (size_t)BB*HH*NPTS/4;
    if (i4 >= total4) return;
    int h = (int)((i4 / (NPTS/4)) % HH);
    float s = sc[h], t = sh[h];
    float4 v = ((float4*)y)[i4];
    v.x = fmaxf(0.0f, v.x*s + t);
    v.y = fmaxf(0.0f, v.y*s + t);
    v.z = fmaxf(0.0f, v.z*s + t);
    v.w = fmaxf(0.0f, v.w*s + t);
    ((float4*)y)[i4] = v;
}

__global__ void softmax_kernel() {
    int b = blockIdx.y;
    int n = blockIdx.x * 256 + threadIdx.x;
    const float* base = g_ls + (size_t)b*KK*NPTS + n;
    float mx = -1e30f;
#pragma unroll
    for (int k = 0; k < KK; k++) mx = fmaxf(mx, base[(size_t)k*NPTS]);
    float s = 0.0f;
#pragma unroll
    for (int k = 0; k < KK; k++) s += __expf(base[(size_t)k*NPTS] - mx);
    float inv = 1.0f / s;
    float* sb = g_score + (size_t)b*KK*NPTS + n;
#pragma unroll
    for (int k = 0; k < KK; k++) sb[(size_t)k*NPTS] = __expf(base[(size_t)k*NPTS] - mx) * inv;
    g_lsn[b*NPTS + n] = mx + logf(s);
}

__global__ void pi_kernel() {
    int k = blockIdx.x, b = blockIdx.y, tid = threadIdx.x;
    const float* p = g_score + (size_t)(b*KK + k) * NPTS;
    float s = 0.0f;
    for (int n = tid; n < NPTS; n += 256) s += p[n];
    __shared__ float r[256];
    r[tid] = s; __syncthreads();
    for (int o = 128; o > 0; o >>= 1) { if (tid < o) r[tid] += r[tid+o]; __syncthreads(); }
    if (tid == 0) g_pi[b*KK + k] = fmaxf(r[0], 1e-4f);
}

__global__ void mu_xyz_kernel(const float* __restrict__ xyz) {
    int k = blockIdx.x, b = blockIdx.y, tid = threadIdx.x;
    const float* sp = g_score + (size_t)(b*KK + k) * NPTS;
    const float* x0 = xyz + (size_t)(b*3 + 0) * NPTS;
    const float* x1 = xyz + (size_t)(b*3 + 1) * NPTS;
    const float* x2 = xyz + (size_t)(b*3 + 2) * NPTS;
    float a0 = 0, a1 = 0, a2 = 0;
    for (int n = tid; n < NPTS; n += 256) {
        float s = sp[n];
        a0 += s * x0[n]; a1 += s * x1[n]; a2 += s * x2[n];
    }
    __shared__ float r[256];
    float acc[3] = {a0, a1, a2};
    for (int d = 0; d < 3; d++) {
        r[tid] = acc[d]; __syncthreads();
        for (int o = 128; o > 0; o >>= 1) { if (tid < o) r[tid] += r[tid+o]; __syncthreads(); }
        if (tid == 0) {
            float invpi = 1.0f / g_pi[b*KK + k];
            g_muxyz[(b*3 + d)*KK + k] = r[0] * invpi;
        }
        __syncthreads();
    }
}

__global__ void invf_kernel(const float* __restrict__ feat) {
    int b = blockIdx.y;
    int n = blockIdx.x * 256 + threadIdx.x;
    float s = 0.0f;
    const float* p = feat + (size_t)b*DD*NPTS + n;
    for (int d = 0; d < DD; d++) { float v = p[(size_t)d*NPTS]; s += v*v; }
    g_invf[b*NPTS + n] = 1.0f / fmaxf(sqrtf(s), 1e-12f);
}

__global__ void invmu_kernel() {
    int b = blockIdx.x, k = threadIdx.x;
    const float4* p = (const float4*)(g_muT + ((size_t)b*KK + k) * DD);
    float s = 0.0f;
    for (int d4 = 0; d4 < DD/4; d4++) {
        float4 v = p[d4];
        s += v.x*v.x + v.y*v.y + v.z*v.z + v.w*v.w;
    }
    g_invmu[b*KK + k] = 1.0f / fmaxf(sqrtf(s), 1e-12f);
}

__global__ void costx_kernel(const float* __restrict__ xyz) {
    int b = blockIdx.y;
    __shared__ float smu[3][64];
    __shared__ float smun[64];
    int tid = threadIdx.x;
    if (tid < 192) smu[tid/64][tid%64] = g_muxyz[b*3*KK + tid];
    __syncthreads();
    if (tid < 64) smun[tid] = smu[0][tid]*smu[0][tid] + smu[1][tid]*smu[1][tid] + smu[2][tid]*smu[2][tid];
    __syncthreads();
    int w = tid >> 5, l = tid & 31;
    int n = blockIdx.x * 8 + w;
    float x0 = xyz[(size_t)(b*3 + 0)*NPTS + n];
    float x1 = xyz[(size_t)(b*3 + 1)*NPTS + n];
    float x2 = xyz[(size_t)(b*3 + 2)*NPTS + n];
    float xn = x0*x0 + x1*x1 + x2*x2;
    float* row = g_costx + ((size_t)b*NPTS + n) * KK;
#pragma unroll
    for (int t = 0; t < 2; t++) {
        int m = l + t*32;
        float d = x0*smu[0][m] + x1*smu[1][m] + x2*smu[2][m];
        row[m] = xn + smun[m] - 2.0f * d;
    }
}

// [b][n][m] -> [b][m][n]
__global__ void transpose_kernel(const float* __restrict__ src, float* __restrict__ dst) {
    __shared__ float t[32][33];
    int b = blockIdx.z;
    int n0 = blockIdx.x * 32, m0 = blockIdx.y * 32;
    int x = threadIdx.x, y = threadIdx.y;
    for (int j = y; j < 32; j += 8)
        t[j][x] = src[((size_t)b*NPTS + n0 + j) * KK + m0 + x];
    __syncthreads();
    for (int j = y; j < 32; j += 8)
        dst[((size_t)b*KK + m0 + j) * NPTS + n0 + x] = t[x][j];
}

// [b][m][n] -> [b][n][m]
__global__ void transposeT_kernel(const float* __restrict__ src, float* __restrict__ dst) {
    __shared__ float t[32][33];
    int b = blockIdx.z;
    int n0 = blockIdx.x * 32, m0 = blockIdx.y * 32;
    int x = threadIdx.x, y = threadIdx.y;
    for (int j = y; j < 32; j += 8)
        t[j][x] = src[((size_t)b*KK + m0 + j) * NPTS + n0 + x];
    __syncthreads();
    for (int j = y; j < 32; j += 8)
        dst[((size_t)b*NPTS + n0 + j) * KK + m0 + x] = t[x][j];
}

__global__ void u_update_kernel() {
    int branch = blockIdx.y;
    const float* C = branch ? g_costf : g_costx;
    const float* v = (branch ? g_v + BB*KK : g_v);
    float* u = (branch ? g_u + BB*NPTS : g_u);
    int r0 = blockIdx.x * 8;
    int b = r0 >> 12;
    __shared__ float vs[64];
    if (threadIdx.x < 64) vs[threadIdx.x] = v[b*KK + threadIdx.x];
    __syncthreads();
    int w = threadIdx.x >> 5, l = threadIdx.x & 31;
    int r = r0 + w;
    const float* Crow = C + (size_t)r * KK;
    float a0 = (vs[l]      - Crow[l])      * INV_EPS;
    float a1 = (vs[l + 32] - Crow[l + 32]) * INV_EPS;
    float mx = fmaxf(a0, a1);
#pragma unroll
    for (int o = 16; o > 0; o >>= 1) mx = fmaxf(mx, __shfl_xor_sync(0xffffffffu, mx, o));
    float s = __expf(a0 - mx) + __expf(a1 - mx);
#pragma unroll
    for (int o = 16; o > 0; o >>= 1) s += __shfl_xor_sync(0xffffffffu, s, o);
    if (l == 0) {
        float epslogp = -SEPS * logf((float)NPTS);
        u[r] = epslogp - SEPS * (mx + logf(s));
    }
}

__global__ void v_update_kernel() {
    int branch = blockIdx.y;
    const float* CT = branch ? g_costfT : g_costxT;
    const float* u = (branch ? g_u + BB*NPTS : g_u);
    float* v = (branch ? g_v + BB*KK : g_v);
    int c = blockIdx.x;
    int b = c >> 6;
    const float* row = CT + (size_t)c * NPTS;
    const float* ub = u + b * NPTS;
    int tid = threadIdx.x;
    float vals[16];
    float mx = -1e30f;
#pragma unroll
    for (int i = 0; i < 16; i++) {
        int n = tid + i * 256;
        vals[i] = (ub[n] - row[n]) * INV_EPS;
        mx = fmaxf(mx, vals[i]);
    }
    __shared__ float r[256];
    r[tid] = mx; __syncthreads();
    for (int o = 128; o > 0; o >>= 1) { if (tid < o) r[tid] = fmaxf(r[tid], r[tid+o]); __syncthreads(); }
    mx = r[0]; __syncthreads();
    float s = 0.0f;
#pragma unroll
    for (int i = 0; i < 16; i++) s += __expf(vals[i] - mx);
    r[tid] = s; __syncthreads();
    for (int o = 128; o > 0; o >>= 1) { if (tid < o) r[tid] += r[tid+o]; __syncthreads(); }
    if (tid == 0) {
        float epslogq = -SEPS * logf((float)KK);
        v[c] = epslogq - SEPS * (mx + logf(r[0]));
    }
}

__global__ void reg_xyz_kernel() {
    int b = blockIdx.x, tid = threadIdx.x;
    float local = 0.0f;
    for (int e = tid; e < KK*KK; e += 256) {
        int m1 = e >> 6, m2 = e & 63;
        float s = 0.0f;
#pragma unroll
        for (int d = 0; d < 3; d++)
            s += g_muxyz[(b*3 + d)*KK + m1] * g_muxyz[(b*3 + d)*KK + m2];
        local += fabsf(s - (m1 == m2 ? 1.0f : 0.0f));
    }
    __shared__ float r[256];
    r[tid] = local; __syncthreads();
    for (int o = 128; o > 0; o >>= 1) { if (tid < o) r[tid] += r[tid+o]; __syncthreads(); }
    if (tid == 0) atomicAdd(&g_acc[2], r[0]);
}

__global__ void reg_fea_kernel() {
    int b = blockIdx.x, tid = threadIdx.x;
    float local = 0.0f;
    for (int e = tid; e < KK*KK; e += 256) {
        int m1 = e >> 6, m2 = e & 63;
        const float4* p1 = (const float4*)(g_muT + ((size_t)b*KK + m1) * DD);
        const float4* p2 = (const float4*)(g_muT + ((size_t)b*KK + m2) * DD);
        float s = 0.0f;
#pragma unroll 4
        for (int d4 = 0; d4 < DD/4; d4++) {
            float4 v1 = p1[d4], v2 = p2[d4];
            s += v1.x*v2.x + v1.y*v2.y + v1.z*v2.z + v1.w*v2.w;
        }
        s *= g_invmu[b*KK + m1] * g_invmu[b*KK + m2];
        local += fabsf(s - (m1 == m2 ? 1.0f : 0.0f));
    }
    __shared__ float r[256];
    r[tid] = local; __syncthreads();
    for (int o = 128; o > 0; o >>= 1) { if (tid < o) r[tid] += r[tid+o]; __syncthreads(); }
    if (tid == 0) atomicAdd(&g_acc[3], r[0]);
}

__global__ void loss_kernel() {
    int branch = blockIdx.y;
    const float* C = branch ? g_costf : g_costx;
    const float* u = (branch ? g_u + BB*NPTS : g_u);
    const float* v = (branch ? g_v + BB*KK : g_v);
    int r0 = blockIdx.x * 8;
    int b = r0 >> 12;
    __shared__ float vs[64];
    if (threadIdx.x < 64) vs[threadIdx.x] = v[b*KK + threadIdx.x];
    __syncthreads();
    int w = threadIdx.x >> 5, l = threadIdx.x & 31;
    int r = r0 + w;
    int n = r & (NPTS - 1);
    const float* Crow = C + (size_t)r * KK;
    float ur = u[r];
    float lsnr = g_lsn[r];
    float acc = 0.0f;
#pragma unroll
    for (int t = 0; t < 2; t++) {
        int m = l + t*32;
        float gma = __expf((ur + vs[m] - Crow[m]) * INV_EPS);
        float lp = g_ls[((size_t)b*KK + m) * NPTS + n] - lsnr;
        acc += gma * lp;
    }
#pragma unroll
    for (int o = 16; o > 0; o >>= 1) acc += __shfl_xor_sync(0xffffffffu, acc, o);
    __shared__ float wsum[8];
    if (l == 0) wsum[w] = acc;
    __syncthreads();
    if (threadIdx.x == 0) {
        float t = 0.0f;
#pragma unroll
        for (int i = 0; i < 8; i++) t += wsum[i];
        atomicAdd(&g_acc[branch], t);
    }
}

__global__ void finalize_kernel(float* __restrict__ out, int out_size) {
    int i = threadIdx.x;
    for (int j = i; j < out_size; j += 32) out[j] = 0.0f;
    __syncwarp();
    if (i == 0) {
        float lx = g_acc[0], lf = g_acc[1], rx = g_acc[2], rf = g_acc[3];
        float loss_xyz = -lx / 8.0f;
        float loss_fea = -lf / 8.0f;
        float reg_fea  = 1e-4f * (rf / (float)(BB*KK*KK));
        float reg_xyz  = 0.001f * 1e-4f * (rx / (float)(BB*KK*KK));
        out[0] = loss_xyz + loss_fea + reg_fea + reg_xyz;
    }
}

// ---------------- launch ----------------
extern "C" void kernel_launch(void* const* d_in, const int* in_sizes, int n_in,
                              void* d_out, int out_size)
{
    const float* feature = (const float*)d_in[0];
    const float* xyz     = (const float*)d_in[1];
    const float* w1      = (const float*)d_in[2];
    const float* b1      = (const float*)d_in[3];
    const float* g1      = (const float*)d_in[4];
    const float* be1     = (const float*)d_in[5];
    const float* w2      = (const float*)d_in[6];
    const float* b2      = (const float*)d_in[7];
    const float* g2      = (const float*)d_in[8];
    const float* be2     = (const float*)d_in[9];
    const float* w3      = (const float*)d_in[10];
    const float* b3      = (const float*)d_in[11];
    float* out = (float*)d_out;

    float* y1; float* y2; float* ls;
    cudaGetSymbolAddress((void**)&y1, g_y1);
    cudaGetSymbolAddress((void**)&y2, g_y2);
    cudaGetSymbolAddress((void**)&ls, g_ls);
    float* sc1; float* sh1; float* sc2; float* sh2;
    cudaGetSymbolAddress((void**)&sc1, g_sc1);
    cudaGetSymbolAddress((void**)&sh1, g_sh1);
    cudaGetSymbolAddress((void**)&sc2, g_sc2);
    cudaGetSymbolAddress((void**)&sh2, g_sh2);
    float* cx; float* cxT; float* cf; float* cfT;
    cudaGetSymbolAddress((void**)&cx,  g_costx);
    cudaGetSymbolAddress((void**)&cxT, g_costxT);
    cudaGetSymbolAddress((void**)&cf,  g_costf);
    cudaGetSymbolAddress((void**)&cfT, g_costfT);
    float* scoreP; float* piP; float* muTP; float* invfP; float* invmuP;
    cudaGetSymbolAddress((void**)&scoreP, g_score);
    cudaGetSymbolAddress((void**)&piP,    g_pi);
    cudaGetSymbolAddress((void**)&muTP,   g_muT);
    cudaGetSymbolAddress((void**)&invfP,  g_invf);
    cudaGetSymbolAddress((void**)&invmuP, g_invmu);

    init_kernel<<<(2*BB*NPTS + 255)/256, 256>>>();

    // layer 1
    mma_gemm_kernel<<<dim3(NPTS/128, HH/128, BB), 256>>>(w1, feature, b1, y1, DD, HH, 0, 0, nullptr, nullptr);
    bn_stats_kernel<<<HH, 256>>>(y1, g1, be1, sc1, sh1);
    bn_relu_kernel<<<(BB*HH*NPTS/4 + 255)/256, 256>>>(y1, sc1, sh1);
    // layer 2
    mma_gemm_kernel<<<dim3(NPTS/128, HH/128, BB), 256>>>(w2, y1, b2, y2, HH, HH, 0, 0, nullptr, nullptr);
    bn_stats_kernel<<<HH, 256>>>(y2, g2, be2, sc2, sh2);
    bn_relu_kernel<<<(BB*HH*NPTS/4 + 255)/256, 256>>>(y2, sc2, sh2);
    // layer 3 (log_score)
    mma_gemm_kernel<<<dim3(NPTS/128, 1, BB), 256>>>(w3, y2, b3, ls, HH, KK, 0, 0, nullptr, nullptr);

    softmax_kernel<<<dim3(NPTS/256, BB), 256>>>();
    pi_kernel<<<dim3(KK, BB), 256>>>();
    mu_xyz_kernel<<<dim3(KK, BB), 256>>>(xyz);

    mma_nt_kernel<<<dim3(DD/128, 1, BB), 256>>>(scoreP, feature, piP, muTP);
    invf_kernel<<<dim3(NPTS/256, BB), 256>>>(feature);
    invmu_kernel<<<BB, 64>>>();

    mma_gemm_kernel<<<dim3(NPTS/128, 1, BB), 256>>>(muTP, feature, nullptr, cfT, DD, KK, KK*DD, 1, invfP, invmuP);
    transposeT_kernel<<<dim3(NPTS/32, KK/32, BB), dim3(32, 8)>>>(cfT, cf);

    costx_kernel<<<dim3(NPTS/8, BB), 256>>>(xyz);
    transpose_kernel<<<dim3(NPTS/32, KK/32, BB), dim3(32, 8)>>>(cx, cxT);

    for (int it = 0; it < 25; it++) {
        u_update_kernel<<<dim3(BB*NPTS/8, 2), 256>>>();
        v_update_kernel<<<dim3(BB*KK, 2), 256>>>();
    }

    reg_xyz_kernel<<<BB, 256>>>();
    reg_fea_kernel<<<BB, 256>>>();
    loss_kernel<<<dim3(BB*NPTS/8, 2), 256>>>();
    finalize_kernel<<<1, 32>>>(out, out_size);
}